// round 8
// baseline (speedup 1.0000x reference)
#include <cuda_runtime.h>
#include <cstdint>

#define NNODES 100000
#define NEDGES 600000
#define HIDDEN 128
#define HEADS  8
#define DH     16
#define NEG_SLOPE 0.2f
#define NSEG (2 * NNODES)            // (sign, node) segments

// ------------------------- scratch (static device globals) -------------------
__device__ float g_feat[2 * NNODES * HIDDEN];   // transformed features, per sign
__device__ float g_el  [2 * NNODES * HEADS];
__device__ float g_er  [2 * NNODES * HEADS];
__device__ float g_tmp [NNODES * HIDDEN];       // MLP hidden
__device__ int   g_cnt [NSEG];                  // per-(sign,node) in-degree
__device__ int   g_scan[NSEG];                  // block-local exclusive scan
__device__ int   g_off [NSEG];                  // global exclusive offsets
__device__ int   g_cur [NSEG];                  // scatter cursors
__device__ int   g_bsum[256];                   // per-block sums for scan
__device__ int   g_srcs[2 * NEDGES];            // src ids, dst-sorted

// ------------------------- init: cnt = 0 -------------------------------------
__global__ void init_cnt() {
    int i = blockIdx.x * blockDim.x + threadIdx.x;
    if (i < NSEG) g_cnt[i] = 0;
}

// ------------------------- histogram of dst ----------------------------------
__global__ void hist_kernel(const int* __restrict__ pd, const int* __restrict__ nd,
                            int e) {
    int i = blockIdx.x * blockDim.x + threadIdx.x;
    if (i >= 2 * e) return;
    int sign = (i >= e);
    int d = sign ? nd[i - e] : pd[i];
    atomicAdd(&g_cnt[sign * NNODES + d], 1);
}

// ------------------------- exclusive scan (3 kernels) ------------------------
__global__ __launch_bounds__(256)
void scan1_kernel(int ntot) {
    __shared__ int wsum[8];
    int tid = threadIdx.x;
    int lane = tid & 31, wid = tid >> 5;
    int base = blockIdx.x * 1024 + tid * 4;
    int v[4];
#pragma unroll
    for (int j = 0; j < 4; j++)
        v[j] = (base + j < ntot) ? g_cnt[base + j] : 0;
    int local = v[0] + v[1] + v[2] + v[3];
    int x = local;
#pragma unroll
    for (int o = 1; o < 32; o <<= 1) {
        int t = __shfl_up_sync(0xffffffffu, x, o);
        if (lane >= o) x += t;
    }
    if (lane == 31) wsum[wid] = x;
    __syncthreads();
    if (tid == 0) {
        int run = 0;
#pragma unroll
        for (int w = 0; w < 8; w++) { int t = wsum[w]; wsum[w] = run; run += t; }
        g_bsum[blockIdx.x] = run;
    }
    __syncthreads();
    int run = wsum[wid] + (x - local);
#pragma unroll
    for (int j = 0; j < 4; j++) {
        if (base + j < ntot) g_scan[base + j] = run;
        run += v[j];
    }
}

__global__ __launch_bounds__(256)
void scan2_kernel(int nb) {
    __shared__ int wsum[8];
    int tid = threadIdx.x;
    int lane = tid & 31, wid = tid >> 5;
    int val = (tid < nb) ? g_bsum[tid] : 0;
    int x = val;
#pragma unroll
    for (int o = 1; o < 32; o <<= 1) {
        int t = __shfl_up_sync(0xffffffffu, x, o);
        if (lane >= o) x += t;
    }
    if (lane == 31) wsum[wid] = x;
    __syncthreads();
    if (tid == 0) {
        int run = 0;
#pragma unroll
        for (int w = 0; w < 8; w++) { int t = wsum[w]; wsum[w] = run; run += t; }
    }
    __syncthreads();
    int excl = wsum[wid] + (x - val);
    if (tid < nb) g_bsum[tid] = excl;
}

__global__ void scan3_kernel(int ntot) {
    int i = blockIdx.x * blockDim.x + threadIdx.x;
    if (i >= ntot) return;
    int off = g_scan[i] + g_bsum[i >> 10];
    g_off[i] = off;
    g_cur[i] = off;
}

// ------------------------- scatter src ids into dst buckets ------------------
__global__ void scatter_kernel(const int* __restrict__ ps, const int* __restrict__ pd,
                               const int* __restrict__ ns, const int* __restrict__ nd,
                               int e) {
    int i = blockIdx.x * blockDim.x + threadIdx.x;
    if (i >= 2 * e) return;
    int sign = (i >= e);
    int j = sign ? i - e : i;
    int s = sign ? ns[j] : ps[j];
    int d = sign ? nd[j] : pd[j];
    int pos = atomicAdd(&g_cur[sign * NNODES + d], 1);
    g_srcs[pos] = s;
}

// ------------------------- CSR aggregation (warp per sign-node) --------------
__global__ __launch_bounds__(256)
void aggregate_kernel(float* __restrict__ out,
                      const float* __restrict__ b_pos,
                      const float* __restrict__ b_neg, int n) {
    int gw = (blockIdx.x * blockDim.x + threadIdx.x) >> 5;
    int lane = threadIdx.x & 31;
    if (gw >= 2 * n) return;
    int sign = (gw >= n);
    int d = sign ? gw - n : gw;
    int seg = sign * NNODES + d;
    int h = lane >> 2;

    float er_h = g_er[(size_t)sign * NNODES * HEADS + (size_t)d * HEADS + h];
    const float* elb = g_el + (size_t)sign * NNODES * HEADS;
    const float* fb  = g_feat + (size_t)sign * NNODES * HIDDEN;

    int start = g_off[seg];
    int end   = start + g_cnt[seg];

    float4 acc = make_float4(0.f, 0.f, 0.f, 0.f);
    float den = 0.f;

    int k = start;
    for (; k + 1 < end; k += 2) {
        int s0 = g_srcs[k];
        int s1 = g_srcs[k + 1];
        float eh0 = elb[(size_t)s0 * HEADS + h] + er_h;
        float eh1 = elb[(size_t)s1 * HEADS + h] + er_h;
        float4 f0 = *(const float4*)&fb[(size_t)s0 * HIDDEN + lane * 4];
        float4 f1 = *(const float4*)&fb[(size_t)s1 * HIDDEN + lane * 4];
        eh0 = (eh0 > 0.f) ? eh0 : NEG_SLOPE * eh0;
        eh1 = (eh1 > 0.f) ? eh1 : NEG_SLOPE * eh1;
        float ex0 = __expf(eh0);
        float ex1 = __expf(eh1);
        den += ex0 + ex1;
        acc.x = fmaf(ex0, f0.x, fmaf(ex1, f1.x, acc.x));
        acc.y = fmaf(ex0, f0.y, fmaf(ex1, f1.y, acc.y));
        acc.z = fmaf(ex0, f0.z, fmaf(ex1, f1.z, acc.z));
        acc.w = fmaf(ex0, f0.w, fmaf(ex1, f1.w, acc.w));
    }
    if (k < end) {
        int s = g_srcs[k];
        float eh = elb[(size_t)s * HEADS + h] + er_h;
        eh = (eh > 0.f) ? eh : NEG_SLOPE * eh;
        float ex = __expf(eh);
        den += ex;
        float4 f = *(const float4*)&fb[(size_t)s * HIDDEN + lane * 4];
        acc.x = fmaf(ex, f.x, acc.x);
        acc.y = fmaf(ex, f.y, acc.y);
        acc.z = fmaf(ex, f.z, acc.z);
        acc.w = fmaf(ex, f.w, acc.w);
    }
    float inv = (den > 0.f) ? (1.0f / den) : 0.0f;
    const float* bias = sign ? b_neg : b_pos;
    float4 bv = *(const float4*)(bias + lane * 4);
    float4 o = make_float4(acc.x * inv + bv.x, acc.y * inv + bv.y,
                           acc.z * inv + bv.z, acc.w * inv + bv.w);
    *(float4*)&out[((size_t)sign * n + d) * HIDDEN + lane * 4] = o;
}

// ------------------------- tf32 helpers --------------------------------------
__device__ __forceinline__ uint32_t f2tf(float f) {
    uint32_t u;
    asm("cvt.rna.tf32.f32 %0, %1;" : "=r"(u) : "f"(f));
    return u;
}

#define MMA_TF32(cr, a, b)                                                     \
    asm volatile("mma.sync.aligned.m16n8k8.row.col.f32.tf32.tf32.f32 "         \
                 "{%0,%1,%2,%3},{%4,%5,%6,%7},{%8,%9},{%0,%1,%2,%3};"          \
                 : "+f"((cr)[0]), "+f"((cr)[1]), "+f"((cr)[2]), "+f"((cr)[3])  \
                 : "r"((a)[0]), "r"((a)[1]), "r"((a)[2]), "r"((a)[3]),         \
                   "r"((b)[0]), "r"((b)[1]))

// ------------------------- tensor-core tf32 GEMM (64-row tiles) --------------
// C[M,NT] = act( [A0|A1][M,K] @ B[K,NT] + bias );  NT in {128, 64}; K in {128,256}.
// CTA tile 64 x NT, 8 warps (4 m-groups of 16 rows x 2 n-halves of NT/2).
// Per warp: 1 m16 x (NT/16) n8 tiles; acc 32 regs -> 3 CTAs/SM.
// Double-buffered smem, one sync per 16-k tile.
// PAIR: grid.y=2 selects pointer set (shared A). el/er epilogue NT=128 only.
template <int NT, bool PAIR>
__global__ __launch_bounds__(256, 3)
void gemm_tc(const float* __restrict__ A0, const float* __restrict__ A1,
             int M, int K,
             const float* __restrict__ B0, const float* __restrict__ B1,
             const float* __restrict__ bias, int relu,
             float* __restrict__ C0, float* __restrict__ C1,
             const float* __restrict__ al0, const float* __restrict__ ar0,
             float* __restrict__ el0, float* __restrict__ er0,
             const float* __restrict__ al1, const float* __restrict__ ar1,
             float* __restrict__ el1, float* __restrict__ er1) {
    constexpr int ASTR = 68;         // 64 + 4; 68 % 32 == 4 -> conflict-free LDS
    constexpr int BSTR = NT + 8;     // % 32 == 8 -> conflict-free LDS
    constexpr int WN   = NT / 2;
    constexpr int NJ   = WN / 8;
    constexpr int BI   = (NT == 128) ? 2 : 1;
    constexpr int ASZ  = 16 * ASTR;  // [k][m]
    constexpr int BSZ  = 16 * BSTR;  // [k][n]

    __shared__ __align__(16) uint32_t As[2 * ASZ];
    __shared__ __align__(16) uint32_t Bs[2 * BSZ];

    const float* B  = B0;
    float*       C  = C0;
    const float* al = al0; const float* ar = ar0;
    float*       el = el0; float*       er = er0;
    if (PAIR && blockIdx.y == 1) {
        B = B1; C = C1; al = al1; ar = ar1; el = el1; er = er1;
    }

    const int tid  = threadIdx.x;
    const int wid  = tid >> 5;
    const int lane = tid & 31;
    const int g    = lane >> 2;
    const int tig  = lane & 3;
    const int wm   = wid & 3;        // m-group (16 rows each)
    const int wn   = wid >> 2;       // n-half (WN cols each)
    const int m0   = blockIdx.x * 64;

    float c[NJ][4];
#pragma unroll
    for (int nj = 0; nj < NJ; nj++)
#pragma unroll
        for (int q = 0; q < 4; q++) c[nj][q] = 0.0f;

    float4 pa;      // A tile 64x16 = 256 float4 -> 1/thread
    float4 pb[2];   // B tile 16xNT -> BI/thread

#define LOAD_A(k0) do {                                                        \
        int row = tid >> 2; int kk = (tid & 3) * 4;                            \
        int grow = m0 + row;                                                   \
        if (grow < M) {                                                        \
            int kg = (k0) + kk;                                                \
            const float* srcp = (kg < 128) ? (A0 + (size_t)grow * 128 + kg)    \
                                           : (A1 + (size_t)grow * 128 + (kg - 128)); \
            pa = *(const float4*)srcp;                                         \
        } else pa = make_float4(0.f, 0.f, 0.f, 0.f);                           \
    } while (0)
#define LOAD_B(k0) do {                                                        \
        _Pragma("unroll")                                                      \
        for (int i = 0; i < BI; i++) {                                         \
            int idx = tid + i * 256;                                           \
            int row, cc;                                                       \
            if (NT == 128) { row = idx >> 5; cc = (idx & 31) * 4; }            \
            else           { row = idx >> 4; cc = (idx & 15) * 4; }            \
            pb[i] = *(const float4*)(B + (size_t)((k0) + row) * NT + cc);      \
        }                                                                      \
    } while (0)
#define COMMIT(p) do {                                                         \
        int row = tid >> 2; int kk = (tid & 3) * 4;                            \
        As[(p) * ASZ + (kk + 0) * ASTR + row] = f2tf(pa.x);                    \
        As[(p) * ASZ + (kk + 1) * ASTR + row] = f2tf(pa.y);                    \
        As[(p) * ASZ + (kk + 2) * ASTR + row] = f2tf(pa.z);                    \
        As[(p) * ASZ + (kk + 3) * ASTR + row] = f2tf(pa.w);                    \
        _Pragma("unroll")                                                      \
        for (int i = 0; i < BI; i++) {                                         \
            int idx = tid + i * 256;                                           \
            int brow, cc;                                                      \
            if (NT == 128) { brow = idx >> 5; cc = (idx & 31) * 4; }           \
            else           { brow = idx >> 4; cc = (idx & 15) * 4; }           \
            uint4 t = make_uint4(f2tf(pb[i].x), f2tf(pb[i].y),                 \
                                 f2tf(pb[i].z), f2tf(pb[i].w));                \
            *(uint4*)&Bs[(p) * BSZ + brow * BSTR + cc] = t;                    \
        }                                                                      \
    } while (0)

    // prologue
    LOAD_A(0); LOAD_B(0);
    COMMIT(0);
    __syncthreads();
    if (K > 16) { LOAD_A(16); LOAD_B(16); }

    int p = 0;
    for (int k0 = 0; k0 < K; k0 += 16) {
        if (k0 + 16 < K) {
            COMMIT(p ^ 1);
            if (k0 + 32 < K) { LOAD_A(k0 + 32); LOAD_B(k0 + 32); }
        }
        const uint32_t* Ap = &As[p * ASZ];
        const uint32_t* Bp = &Bs[p * BSZ];
        const int mb = wm * 16;
#pragma unroll
        for (int ks = 0; ks < 16; ks += 8) {
            uint32_t af[4];
            af[0] = Ap[(ks + tig)     * ASTR + mb + g];
            af[1] = Ap[(ks + tig)     * ASTR + mb + 8 + g];
            af[2] = Ap[(ks + tig + 4) * ASTR + mb + g];
            af[3] = Ap[(ks + tig + 4) * ASTR + mb + 8 + g];
            uint32_t bf[NJ][2];
#pragma unroll
            for (int nj = 0; nj < NJ; nj++) {
                int nb = wn * WN + nj * 8;
                bf[nj][0] = Bp[(ks + tig)     * BSTR + nb + g];
                bf[nj][1] = Bp[(ks + tig + 4) * BSTR + nb + g];
            }
#pragma unroll
            for (int nj = 0; nj < NJ; nj++)
                MMA_TF32(c[nj], af, bf[nj]);
        }
        __syncthreads();
        p ^= 1;
    }
#undef LOAD_A
#undef LOAD_B
#undef COMMIT

    // ---- fused el/er epilogue (NT=128 path only) ----
    if (NT == 128 && el != nullptr) {
#pragma unroll
        for (int h = 0; h < 4; h++) {
            float e0 = 0.f, e1 = 0.f, r0v = 0.f, r1v = 0.f;
#pragma unroll
            for (int q = 0; q < 2; q++) {
                int nj = 2 * h + q;
                int col = wn * 64 + nj * 8 + 2 * tig;
                float a0 = al[col], a1 = al[col + 1];
                float b0 = ar[col], b1 = ar[col + 1];
                e0  += c[nj][0] * a0 + c[nj][1] * a1;   // row g
                e1  += c[nj][2] * a0 + c[nj][3] * a1;   // row g+8
                r0v += c[nj][0] * b0 + c[nj][1] * b1;
                r1v += c[nj][2] * b0 + c[nj][3] * b1;
            }
            e0  += __shfl_xor_sync(0xffffffffu, e0, 1);
            e0  += __shfl_xor_sync(0xffffffffu, e0, 2);
            e1  += __shfl_xor_sync(0xffffffffu, e1, 1);
            e1  += __shfl_xor_sync(0xffffffffu, e1, 2);
            r0v += __shfl_xor_sync(0xffffffffu, r0v, 1);
            r0v += __shfl_xor_sync(0xffffffffu, r0v, 2);
            r1v += __shfl_xor_sync(0xffffffffu, r1v, 1);
            r1v += __shfl_xor_sync(0xffffffffu, r1v, 2);
            if (tig == 0) {
                int hg = wn * 4 + h;
                int ra = m0 + wm * 16 + g;
                int rb = ra + 8;
                if (ra < M) { el[ra * HEADS + hg] = e0;  er[ra * HEADS + hg] = r0v; }
                if (rb < M) { el[rb * HEADS + hg] = e1;  er[rb * HEADS + hg] = r1v; }
            }
        }
    }

    // ---- store C with bias/relu ----
    {
        int ra = m0 + wm * 16 + g;
        int rb = ra + 8;
#pragma unroll
        for (int nj = 0; nj < NJ; nj++) {
            int col = wn * WN + nj * 8 + 2 * tig;
            float bx = 0.f, by = 0.f;
            if (bias) { bx = bias[col]; by = bias[col + 1]; }
            float v0 = c[nj][0] + bx, v1 = c[nj][1] + by;
            float v2 = c[nj][2] + bx, v3 = c[nj][3] + by;
            if (relu) {
                v0 = fmaxf(v0, 0.f); v1 = fmaxf(v1, 0.f);
                v2 = fmaxf(v2, 0.f); v3 = fmaxf(v3, 0.f);
            }
            if (ra < M) *(float2*)&C[(size_t)ra * NT + col] = make_float2(v0, v1);
            if (rb < M) *(float2*)&C[(size_t)rb * NT + col] = make_float2(v2, v3);
        }
    }
}

// ------------------------- launcher ------------------------------------------
extern "C" void kernel_launch(void* const* d_in, const int* in_sizes, int n_in,
                              void* d_out, int out_size) {
    const float* features = (const float*)d_in[0];
    const int*   pos_src  = (const int*)d_in[1];
    const int*   pos_dst  = (const int*)d_in[2];
    const int*   neg_src  = (const int*)d_in[3];
    const int*   neg_dst  = (const int*)d_in[4];
    const float* W_pos    = (const float*)d_in[5];
    const float* al_pos   = (const float*)d_in[6];
    const float* ar_pos   = (const float*)d_in[7];
    const float* b_pos    = (const float*)d_in[8];
    const float* W_neg    = (const float*)d_in[9];
    const float* al_neg   = (const float*)d_in[10];
    const float* ar_neg   = (const float*)d_in[11];
    const float* b_neg    = (const float*)d_in[12];
    const float* W1       = (const float*)d_in[13];
    const float* b1       = (const float*)d_in[14];
    const float* W2       = (const float*)d_in[15];
    const float* b2       = (const float*)d_in[16];
    float* out = (float*)d_out;

    int n = in_sizes[0] / HIDDEN;   // 100000
    int e = in_sizes[1];            // 600000

    void* p;
    cudaGetSymbolAddress(&p, g_feat);  float* featp = (float*)p;
    cudaGetSymbolAddress(&p, g_tmp);   float* tmpp  = (float*)p;
    cudaGetSymbolAddress(&p, g_el);    float* elp   = (float*)p;
    cudaGetSymbolAddress(&p, g_er);    float* erp   = (float*)p;

    float* h_pos   = out;
    float* h_neg   = out + (size_t)n * HIDDEN;
    float* h_final = out + (size_t)2 * n * HIDDEN;

    int gb   = (n + 63) / 64;
    int nseg = 2 * n;
    int nb   = (nseg + 1023) / 1024;

    // 1) CSR build: counts + histogram
    init_cnt<<<(NSEG + 255) / 256, 256>>>();
    hist_kernel<<<(2 * e + 255) / 256, 256>>>(pos_dst, neg_dst, e);

    // 2) feature transform GEMMs (tf32, both signs in one launch via grid.y)
    {
        dim3 grid(gb, 2);
        gemm_tc<128, true><<<grid, 256>>>(
            features, features, n, HIDDEN,
            W_pos, W_neg, nullptr, 0,
            featp, featp + (size_t)NNODES * HIDDEN,
            al_pos, ar_pos, elp, erp,
            al_neg, ar_neg,
            elp + (size_t)NNODES * HEADS, erp + (size_t)NNODES * HEADS);
    }

    // 3) CSR: scan + scatter
    scan1_kernel<<<nb, 256>>>(nseg);
    scan2_kernel<<<1, 256>>>(nb);
    scan3_kernel<<<(nseg + 255) / 256, 256>>>(nseg);
    scatter_kernel<<<(2 * e + 255) / 256, 256>>>(pos_src, pos_dst, neg_src, neg_dst, e);

    // 4) fused softmax + aggregation + normalize + bias (h_pos | h_neg)
    {
        int gwb = (2 * n + 7) / 8;
        aggregate_kernel<<<gwb, 256>>>(out, b_pos, b_neg, n);
    }

    // 5) MLP: h_final = relu([h_pos|h_neg] @ W1 + b1) @ W2 + b2
    gemm_tc<128, false><<<gb, 256>>>(
        h_pos, h_neg, n, 2 * HIDDEN,
        W1, nullptr, b1, 1, tmpp, nullptr,
        nullptr, nullptr, nullptr, nullptr,
        nullptr, nullptr, nullptr, nullptr);
    gemm_tc<64, false><<<gb, 256>>>(
        tmpp, tmpp, n, HIDDEN,
        W2, nullptr, b2, 0, h_final, nullptr,
        nullptr, nullptr, nullptr, nullptr,
        nullptr, nullptr, nullptr, nullptr);
}

// round 9
// speedup vs baseline: 1.1846x; 1.1846x over previous
#include <cuda_runtime.h>
#include <cuda_fp16.h>
#include <cstdint>

#define NNODES 100000
#define NEDGES 600000
#define HIDDEN 128
#define HEADS  8
#define DH     16
#define NEG_SLOPE 0.2f
#define NSEG (2 * NNODES)            // (sign, node) segments

// ------------------------- scratch (static device globals) -------------------
__device__ __half g_feat16[2 * NNODES * HIDDEN]; // transformed features (fp16), per sign
__device__ float g_el  [2 * NNODES * HEADS];
__device__ float g_er  [2 * NNODES * HEADS];
__device__ float g_tmp [NNODES * HIDDEN];       // MLP hidden
__device__ int   g_cnt [NSEG];                  // per-(sign,node) in-degree
__device__ int   g_scan[NSEG];                  // block-local exclusive scan
__device__ int   g_off [NSEG];                  // global exclusive offsets
__device__ int   g_cur [NSEG];                  // scatter cursors
__device__ int   g_bsum[256];                   // per-block sums for scan
__device__ int   g_srcs[2 * NEDGES];            // src ids, dst-sorted

// ------------------------- init: cnt = 0 -------------------------------------
__global__ void init_cnt() {
    int i = blockIdx.x * blockDim.x + threadIdx.x;
    if (i < NSEG) g_cnt[i] = 0;
}

// ------------------------- histogram of dst ----------------------------------
__global__ void hist_kernel(const int* __restrict__ pd, const int* __restrict__ nd,
                            int e) {
    int i = blockIdx.x * blockDim.x + threadIdx.x;
    if (i >= 2 * e) return;
    int sign = (i >= e);
    int d = sign ? nd[i - e] : pd[i];
    atomicAdd(&g_cnt[sign * NNODES + d], 1);
}

// ------------------------- exclusive scan (3 kernels) ------------------------
__global__ __launch_bounds__(256)
void scan1_kernel(int ntot) {
    __shared__ int wsum[8];
    int tid = threadIdx.x;
    int lane = tid & 31, wid = tid >> 5;
    int base = blockIdx.x * 1024 + tid * 4;
    int v[4];
#pragma unroll
    for (int j = 0; j < 4; j++)
        v[j] = (base + j < ntot) ? g_cnt[base + j] : 0;
    int local = v[0] + v[1] + v[2] + v[3];
    int x = local;
#pragma unroll
    for (int o = 1; o < 32; o <<= 1) {
        int t = __shfl_up_sync(0xffffffffu, x, o);
        if (lane >= o) x += t;
    }
    if (lane == 31) wsum[wid] = x;
    __syncthreads();
    if (tid == 0) {
        int run = 0;
#pragma unroll
        for (int w = 0; w < 8; w++) { int t = wsum[w]; wsum[w] = run; run += t; }
        g_bsum[blockIdx.x] = run;
    }
    __syncthreads();
    int run = wsum[wid] + (x - local);
#pragma unroll
    for (int j = 0; j < 4; j++) {
        if (base + j < ntot) g_scan[base + j] = run;
        run += v[j];
    }
}

__global__ __launch_bounds__(256)
void scan2_kernel(int nb) {
    __shared__ int wsum[8];
    int tid = threadIdx.x;
    int lane = tid & 31, wid = tid >> 5;
    int val = (tid < nb) ? g_bsum[tid] : 0;
    int x = val;
#pragma unroll
    for (int o = 1; o < 32; o <<= 1) {
        int t = __shfl_up_sync(0xffffffffu, x, o);
        if (lane >= o) x += t;
    }
    if (lane == 31) wsum[wid] = x;
    __syncthreads();
    if (tid == 0) {
        int run = 0;
#pragma unroll
        for (int w = 0; w < 8; w++) { int t = wsum[w]; wsum[w] = run; run += t; }
    }
    __syncthreads();
    int excl = wsum[wid] + (x - val);
    if (tid < nb) g_bsum[tid] = excl;
}

__global__ void scan3_kernel(int ntot) {
    int i = blockIdx.x * blockDim.x + threadIdx.x;
    if (i >= ntot) return;
    int off = g_scan[i] + g_bsum[i >> 10];
    g_off[i] = off;
    g_cur[i] = off;
}

// ------------------------- scatter src ids into dst buckets ------------------
__global__ void scatter_kernel(const int* __restrict__ ps, const int* __restrict__ pd,
                               const int* __restrict__ ns, const int* __restrict__ nd,
                               int e) {
    int i = blockIdx.x * blockDim.x + threadIdx.x;
    if (i >= 2 * e) return;
    int sign = (i >= e);
    int j = sign ? i - e : i;
    int s = sign ? ns[j] : ps[j];
    int d = sign ? nd[j] : pd[j];
    int pos = atomicAdd(&g_cur[sign * NNODES + d], 1);
    g_srcs[pos] = s;
}

// ------------------------- CSR aggregation (warp per sign-node) --------------
// lane l owns dims [4l..4l+3] (fp16 gather, 8B/lane); head = l/4.
__global__ __launch_bounds__(256)
void aggregate_kernel(float* __restrict__ out,
                      const float* __restrict__ b_pos,
                      const float* __restrict__ b_neg, int n) {
    int gw = (blockIdx.x * blockDim.x + threadIdx.x) >> 5;
    int lane = threadIdx.x & 31;
    if (gw >= 2 * n) return;
    int sign = (gw >= n);
    int d = sign ? gw - n : gw;
    int seg = sign * NNODES + d;
    int h = lane >> 2;

    float er_h = g_er[(size_t)sign * NNODES * HEADS + (size_t)d * HEADS + h];
    const float* elb = g_el + (size_t)sign * NNODES * HEADS;
    const __half* fb = g_feat16 + (size_t)sign * NNODES * HIDDEN;

    int start = g_off[seg];
    int end   = start + g_cnt[seg];

    float4 acc = make_float4(0.f, 0.f, 0.f, 0.f);
    float den = 0.f;

    int k = start;
    for (; k + 1 < end; k += 2) {
        int s0 = g_srcs[k];
        int s1 = g_srcs[k + 1];
        float eh0 = elb[(size_t)s0 * HEADS + h] + er_h;
        float eh1 = elb[(size_t)s1 * HEADS + h] + er_h;
        __half2 a0 = *(const __half2*)&fb[(size_t)s0 * HIDDEN + lane * 4];
        __half2 a1 = *(const __half2*)&fb[(size_t)s0 * HIDDEN + lane * 4 + 2];
        __half2 b0 = *(const __half2*)&fb[(size_t)s1 * HIDDEN + lane * 4];
        __half2 b1 = *(const __half2*)&fb[(size_t)s1 * HIDDEN + lane * 4 + 2];
        eh0 = (eh0 > 0.f) ? eh0 : NEG_SLOPE * eh0;
        eh1 = (eh1 > 0.f) ? eh1 : NEG_SLOPE * eh1;
        float ex0 = __expf(eh0);
        float ex1 = __expf(eh1);
        den += ex0 + ex1;
        float2 f0a = __half22float2(a0), f0b = __half22float2(a1);
        float2 f1a = __half22float2(b0), f1b = __half22float2(b1);
        acc.x = fmaf(ex0, f0a.x, fmaf(ex1, f1a.x, acc.x));
        acc.y = fmaf(ex0, f0a.y, fmaf(ex1, f1a.y, acc.y));
        acc.z = fmaf(ex0, f0b.x, fmaf(ex1, f1b.x, acc.z));
        acc.w = fmaf(ex0, f0b.y, fmaf(ex1, f1b.y, acc.w));
    }
    if (k < end) {
        int s = g_srcs[k];
        float eh = elb[(size_t)s * HEADS + h] + er_h;
        eh = (eh > 0.f) ? eh : NEG_SLOPE * eh;
        float ex = __expf(eh);
        den += ex;
        __half2 a0 = *(const __half2*)&fb[(size_t)s * HIDDEN + lane * 4];
        __half2 a1 = *(const __half2*)&fb[(size_t)s * HIDDEN + lane * 4 + 2];
        float2 fa = __half22float2(a0), fbv = __half22float2(a1);
        acc.x = fmaf(ex, fa.x, acc.x);
        acc.y = fmaf(ex, fa.y, acc.y);
        acc.z = fmaf(ex, fbv.x, acc.z);
        acc.w = fmaf(ex, fbv.y, acc.w);
    }
    float inv = (den > 0.f) ? (1.0f / den) : 0.0f;
    const float* bias = sign ? b_neg : b_pos;
    float4 bv = *(const float4*)(bias + lane * 4);
    float4 o = make_float4(acc.x * inv + bv.x, acc.y * inv + bv.y,
                           acc.z * inv + bv.z, acc.w * inv + bv.w);
    *(float4*)&out[((size_t)sign * n + d) * HIDDEN + lane * 4] = o;
}

// ------------------------- tf32 helpers --------------------------------------
__device__ __forceinline__ uint32_t f2tf(float f) {
    uint32_t u;
    asm("cvt.rna.tf32.f32 %0, %1;" : "=r"(u) : "f"(f));
    return u;
}

#define MMA_TF32(cr, a, b)                                                     \
    asm volatile("mma.sync.aligned.m16n8k8.row.col.f32.tf32.tf32.f32 "         \
                 "{%0,%1,%2,%3},{%4,%5,%6,%7},{%8,%9},{%0,%1,%2,%3};"          \
                 : "+f"((cr)[0]), "+f"((cr)[1]), "+f"((cr)[2]), "+f"((cr)[3])  \
                 : "r"((a)[0]), "r"((a)[1]), "r"((a)[2]), "r"((a)[3]),         \
                   "r"((b)[0]), "r"((b)[1]))

// ------------------------- tensor-core tf32 GEMM (double-buffered) -----------
// R7 design: CTA tile 128 x NT, 8 warps (4x2), warp tile 32 x NT/2.
// HOUT: store C as fp16 (__half2 pairs). PAIR: grid.y picks pointer set.
template <int NT, bool PAIR, bool HOUT>
__global__ __launch_bounds__(256, 2)
void gemm_tc(const float* __restrict__ A0, const float* __restrict__ A1,
             int M, int K,
             const float* __restrict__ B0, const float* __restrict__ B1,
             const float* __restrict__ bias, int relu,
             void* __restrict__ C0, void* __restrict__ C1,
             const float* __restrict__ al0, const float* __restrict__ ar0,
             float* __restrict__ el0, float* __restrict__ er0,
             const float* __restrict__ al1, const float* __restrict__ ar1,
             float* __restrict__ el1, float* __restrict__ er1) {
    constexpr int ASTR = 20;
    constexpr int BSTR = NT + 8;
    constexpr int WN   = NT / 2;
    constexpr int NJ   = WN / 8;
    constexpr int BI   = (NT == 128) ? 2 : 1;
    constexpr int ASZ  = 128 * ASTR;
    constexpr int BSZ  = 16 * BSTR;

    __shared__ __align__(16) uint32_t As[2 * ASZ];
    __shared__ __align__(16) uint32_t Bs[2 * BSZ];

    const float* B  = B0;
    void*        C  = C0;
    const float* al = al0; const float* ar = ar0;
    float*       el = el0; float*       er = er0;
    if (PAIR && blockIdx.y == 1) {
        B = B1; C = C1; al = al1; ar = ar1; el = el1; er = er1;
    }

    const int tid  = threadIdx.x;
    const int wid  = tid >> 5;
    const int lane = tid & 31;
    const int g    = lane >> 2;
    const int tig  = lane & 3;
    const int wm   = wid & 3;
    const int wn   = wid >> 2;
    const int m0   = blockIdx.x * 128;

    float c[2][NJ][4];
#pragma unroll
    for (int mi = 0; mi < 2; mi++)
#pragma unroll
        for (int nj = 0; nj < NJ; nj++)
#pragma unroll
            for (int q = 0; q < 4; q++) c[mi][nj][q] = 0.0f;

    float4 pa[2], pb[2];

#define LOAD_A(k0, i, dstv) do {                                               \
        int idx = tid + (i) * 256;                                             \
        int row = idx >> 2; int kk = (idx & 3) * 4;                            \
        int grow = m0 + row;                                                   \
        if (grow < M) {                                                        \
            int kg = (k0) + kk;                                                \
            const float* srcp = (kg < 128) ? (A0 + (size_t)grow * 128 + kg)    \
                                           : (A1 + (size_t)grow * 128 + (kg - 128)); \
            dstv = *(const float4*)srcp;                                       \
        } else dstv = make_float4(0.f, 0.f, 0.f, 0.f);                         \
    } while (0)
#define LOAD_B(k0, i, dstv) do {                                               \
        int idx = tid + (i) * 256;                                             \
        int row, cc;                                                           \
        if (NT == 128) { row = idx >> 5; cc = (idx & 31) * 4; }                \
        else           { row = idx >> 4; cc = (idx & 15) * 4; }                \
        dstv = *(const float4*)(B + (size_t)((k0) + row) * NT + cc);           \
    } while (0)
#define COMMIT(p) do {                                                         \
        _Pragma("unroll")                                                      \
        for (int i = 0; i < 2; i++) {                                          \
            int idx = tid + i * 256;                                           \
            int row = idx >> 2; int kk = (idx & 3) * 4;                        \
            uint4 t = make_uint4(f2tf(pa[i].x), f2tf(pa[i].y),                 \
                                 f2tf(pa[i].z), f2tf(pa[i].w));                \
            *(uint4*)&As[(p) * ASZ + row * ASTR + kk] = t;                     \
        }                                                                      \
        _Pragma("unroll")                                                      \
        for (int i = 0; i < BI; i++) {                                         \
            int idx = tid + i * 256;                                           \
            int row, cc;                                                       \
            if (NT == 128) { row = idx >> 5; cc = (idx & 31) * 4; }            \
            else           { row = idx >> 4; cc = (idx & 15) * 4; }            \
            uint4 t = make_uint4(f2tf(pb[i].x), f2tf(pb[i].y),                 \
                                 f2tf(pb[i].z), f2tf(pb[i].w));                \
            *(uint4*)&Bs[(p) * BSZ + row * BSTR + cc] = t;                     \
        }                                                                      \
    } while (0)

    LOAD_A(0, 0, pa[0]); LOAD_A(0, 1, pa[1]);
    LOAD_B(0, 0, pb[0]);
    if (BI == 2) LOAD_B(0, 1, pb[1]);
    COMMIT(0);
    __syncthreads();
    if (K > 16) {
        LOAD_A(16, 0, pa[0]); LOAD_A(16, 1, pa[1]);
        LOAD_B(16, 0, pb[0]);
        if (BI == 2) LOAD_B(16, 1, pb[1]);
    }

    int p = 0;
    for (int k0 = 0; k0 < K; k0 += 16) {
        if (k0 + 16 < K) {
            COMMIT(p ^ 1);
            if (k0 + 32 < K) {
                LOAD_A(k0 + 32, 0, pa[0]); LOAD_A(k0 + 32, 1, pa[1]);
                LOAD_B(k0 + 32, 0, pb[0]);
                if (BI == 2) LOAD_B(k0 + 32, 1, pb[1]);
            }
        }
        const uint32_t* Ap = &As[p * ASZ];
        const uint32_t* Bp = &Bs[p * BSZ];
#pragma unroll
        for (int ks = 0; ks < 16; ks += 8) {
            uint32_t af[2][4];
#pragma unroll
            for (int mi = 0; mi < 2; mi++) {
                int mb = wm * 32 + mi * 16;
                af[mi][0] = Ap[(mb + g)     * ASTR + ks + tig];
                af[mi][1] = Ap[(mb + 8 + g) * ASTR + ks + tig];
                af[mi][2] = Ap[(mb + g)     * ASTR + ks + tig + 4];
                af[mi][3] = Ap[(mb + 8 + g) * ASTR + ks + tig + 4];
            }
            uint32_t bf[NJ][2];
#pragma unroll
            for (int nj = 0; nj < NJ; nj++) {
                int nb = wn * WN + nj * 8;
                bf[nj][0] = Bp[(ks + tig)     * BSTR + nb + g];
                bf[nj][1] = Bp[(ks + tig + 4) * BSTR + nb + g];
            }
#pragma unroll
            for (int mi = 0; mi < 2; mi++)
#pragma unroll
                for (int nj = 0; nj < NJ; nj++)
                    MMA_TF32(c[mi][nj], af[mi], bf[nj]);
        }
        __syncthreads();
        p ^= 1;
    }
#undef LOAD_A
#undef LOAD_B
#undef COMMIT

    // ---- fused el/er epilogue (NT=128 path only) ----
    if (NT == 128 && el != nullptr) {
#pragma unroll
        for (int mi = 0; mi < 2; mi++) {
#pragma unroll
            for (int h = 0; h < 4; h++) {
                float e0 = 0.f, e1 = 0.f, r0v = 0.f, r1v = 0.f;
#pragma unroll
                for (int q = 0; q < 2; q++) {
                    int nj = 2 * h + q;
                    int col = wn * 64 + nj * 8 + 2 * tig;
                    float a0 = al[col], a1 = al[col + 1];
                    float b0 = ar[col], b1 = ar[col + 1];
                    e0  += c[mi][nj][0] * a0 + c[mi][nj][1] * a1;
                    e1  += c[mi][nj][2] * a0 + c[mi][nj][3] * a1;
                    r0v += c[mi][nj][0] * b0 + c[mi][nj][1] * b1;
                    r1v += c[mi][nj][2] * b0 + c[mi][nj][3] * b1;
                }
                e0  += __shfl_xor_sync(0xffffffffu, e0, 1);
                e0  += __shfl_xor_sync(0xffffffffu, e0, 2);
                e1  += __shfl_xor_sync(0xffffffffu, e1, 1);
                e1  += __shfl_xor_sync(0xffffffffu, e1, 2);
                r0v += __shfl_xor_sync(0xffffffffu, r0v, 1);
                r0v += __shfl_xor_sync(0xffffffffu, r0v, 2);
                r1v += __shfl_xor_sync(0xffffffffu, r1v, 1);
                r1v += __shfl_xor_sync(0xffffffffu, r1v, 2);
                if (tig == 0) {
                    int hg = wn * 4 + h;
                    int ra = m0 + wm * 32 + mi * 16 + g;
                    int rb = ra + 8;
                    if (ra < M) { el[ra * HEADS + hg] = e0;  er[ra * HEADS + hg] = r0v; }
                    if (rb < M) { el[rb * HEADS + hg] = e1;  er[rb * HEADS + hg] = r1v; }
                }
            }
        }
    }

    // ---- store C with bias/relu (fp32 or fp16) ----
#pragma unroll
    for (int mi = 0; mi < 2; mi++) {
        int ra = m0 + wm * 32 + mi * 16 + g;
        int rb = ra + 8;
#pragma unroll
        for (int nj = 0; nj < NJ; nj++) {
            int col = wn * WN + nj * 8 + 2 * tig;
            float bx = 0.f, by = 0.f;
            if (bias) { bx = bias[col]; by = bias[col + 1]; }
            float v0 = c[mi][nj][0] + bx, v1 = c[mi][nj][1] + by;
            float v2 = c[mi][nj][2] + bx, v3 = c[mi][nj][3] + by;
            if (relu) {
                v0 = fmaxf(v0, 0.f); v1 = fmaxf(v1, 0.f);
                v2 = fmaxf(v2, 0.f); v3 = fmaxf(v3, 0.f);
            }
            if (HOUT) {
                __half* C16 = (__half*)C;
                if (ra < M) *(__half2*)&C16[(size_t)ra * NT + col] = __floats2half2_rn(v0, v1);
                if (rb < M) *(__half2*)&C16[(size_t)rb * NT + col] = __floats2half2_rn(v2, v3);
            } else {
                float* C32 = (float*)C;
                if (ra < M) *(float2*)&C32[(size_t)ra * NT + col] = make_float2(v0, v1);
                if (rb < M) *(float2*)&C32[(size_t)rb * NT + col] = make_float2(v2, v3);
            }
        }
    }
}

// ------------------------- launcher ------------------------------------------
extern "C" void kernel_launch(void* const* d_in, const int* in_sizes, int n_in,
                              void* d_out, int out_size) {
    const float* features = (const float*)d_in[0];
    const int*   pos_src  = (const int*)d_in[1];
    const int*   pos_dst  = (const int*)d_in[2];
    const int*   neg_src  = (const int*)d_in[3];
    const int*   neg_dst  = (const int*)d_in[4];
    const float* W_pos    = (const float*)d_in[5];
    const float* al_pos   = (const float*)d_in[6];
    const float* ar_pos   = (const float*)d_in[7];
    const float* b_pos    = (const float*)d_in[8];
    const float* W_neg    = (const float*)d_in[9];
    const float* al_neg   = (const float*)d_in[10];
    const float* ar_neg   = (const float*)d_in[11];
    const float* b_neg    = (const float*)d_in[12];
    const float* W1       = (const float*)d_in[13];
    const float* b1       = (const float*)d_in[14];
    const float* W2       = (const float*)d_in[15];
    const float* b2       = (const float*)d_in[16];
    float* out = (float*)d_out;

    int n = in_sizes[0] / HIDDEN;   // 100000
    int e = in_sizes[1];            // 600000

    void* p;
    cudaGetSymbolAddress(&p, g_feat16); __half* featp = (__half*)p;
    cudaGetSymbolAddress(&p, g_tmp);    float*  tmpp  = (float*)p;
    cudaGetSymbolAddress(&p, g_el);     float*  elp   = (float*)p;
    cudaGetSymbolAddress(&p, g_er);     float*  erp   = (float*)p;

    float* h_pos   = out;
    float* h_neg   = out + (size_t)n * HIDDEN;
    float* h_final = out + (size_t)2 * n * HIDDEN;

    int gb   = (n + 127) / 128;
    int nseg = 2 * n;
    int nb   = (nseg + 1023) / 1024;

    // Fork a side stream for the CSR build (independent of the feature GEMMs).
    // Stream/event creation is host-side and happens only at capture time;
    // graph replays are unaffected. Not destroyed (capture-safe; few calls).
    cudaStream_t s1;
    cudaEvent_t ev_fork, ev_join;
    cudaStreamCreateWithFlags(&s1, cudaStreamNonBlocking);
    cudaEventCreateWithFlags(&ev_fork, cudaEventDisableTiming);
    cudaEventCreateWithFlags(&ev_join, cudaEventDisableTiming);

    cudaEventRecord(ev_fork, 0);
    cudaStreamWaitEvent(s1, ev_fork, 0);

    // --- side stream: CSR build ---
    init_cnt<<<(NSEG + 255) / 256, 256, 0, s1>>>();
    hist_kernel<<<(2 * e + 255) / 256, 256, 0, s1>>>(pos_dst, neg_dst, e);
    scan1_kernel<<<nb, 256, 0, s1>>>(nseg);
    scan2_kernel<<<1, 256, 0, s1>>>(nb);
    scan3_kernel<<<(nseg + 255) / 256, 256, 0, s1>>>(nseg);
    scatter_kernel<<<(2 * e + 255) / 256, 256, 0, s1>>>(pos_src, pos_dst, neg_src, neg_dst, e);
    cudaEventRecord(ev_join, s1);

    // --- main stream: feature transform GEMMs (tf32, both signs, fp16 out) ---
    {
        dim3 grid(gb, 2);
        gemm_tc<128, true, true><<<grid, 256>>>(
            features, features, n, HIDDEN,
            W_pos, W_neg, nullptr, 0,
            featp, featp + (size_t)NNODES * HIDDEN,
            al_pos, ar_pos, elp, erp,
            al_neg, ar_neg,
            elp + (size_t)NNODES * HEADS, erp + (size_t)NNODES * HEADS);
    }

    // join: aggregation needs both CSR and features
    cudaStreamWaitEvent(0, ev_join, 0);

    // --- fused softmax + aggregation + normalize + bias (h_pos | h_neg) ---
    {
        int gwb = (2 * n + 7) / 8;
        aggregate_kernel<<<gwb, 256>>>(out, b_pos, b_neg, n);
    }

    // --- MLP: h_final = relu([h_pos|h_neg] @ W1 + b1) @ W2 + b2 ---
    gemm_tc<128, false, false><<<gb, 256>>>(
        h_pos, h_neg, n, 2 * HIDDEN,
        W1, nullptr, b1, 1, tmpp, nullptr,
        nullptr, nullptr, nullptr, nullptr,
        nullptr, nullptr, nullptr, nullptr);
    gemm_tc<64, false, false><<<gb, 256>>>(
        tmpp, tmpp, n, HIDDEN,
        W2, nullptr, b2, 0, h_final, nullptr,
        nullptr, nullptr, nullptr, nullptr,
        nullptr, nullptr, nullptr, nullptr);
}

// round 10
// speedup vs baseline: 1.3102x; 1.1061x over previous
#include <cuda_runtime.h>
#include <cuda_fp16.h>
#include <cstdint>

#define NNODES 100000
#define NEDGES 600000
#define HIDDEN 128
#define HEADS  8
#define DH     16
#define NEG_SLOPE 0.2f
#define NSEG (2 * NNODES)            // (sign, node) segments

// ------------------------- scratch (static device globals) -------------------
__device__ __half g_feat16[2 * NNODES * HIDDEN]; // transformed features (fp16), per sign
__device__ float g_el  [2 * NNODES * HEADS];
__device__ float g_er  [2 * NNODES * HEADS];
__device__ float g_tmp [NNODES * HIDDEN];       // MLP hidden
__device__ int   g_cnt [NSEG];                  // per-(sign,node) in-degree
__device__ int   g_scan[NSEG];                  // block-local exclusive scan
__device__ int   g_off [NSEG];                  // global exclusive offsets
__device__ int   g_cur [NSEG];                  // scatter cursors
__device__ int   g_bsum[256];                   // per-block sums for scan
__device__ int   g_srcs[2 * NEDGES];            // src ids, dst-sorted

// ------------------------- init: cnt = 0 -------------------------------------
__global__ void init_cnt() {
    int i = blockIdx.x * blockDim.x + threadIdx.x;
    if (i < NSEG) g_cnt[i] = 0;
}

// ------------------------- histogram of dst ----------------------------------
__global__ void hist_kernel(const int* __restrict__ pd, const int* __restrict__ nd,
                            int e) {
    int i = blockIdx.x * blockDim.x + threadIdx.x;
    if (i >= 2 * e) return;
    int sign = (i >= e);
    int d = sign ? nd[i - e] : pd[i];
    atomicAdd(&g_cnt[sign * NNODES + d], 1);
}

// ------------------------- exclusive scan (3 kernels) ------------------------
__global__ __launch_bounds__(256)
void scan1_kernel(int ntot) {
    __shared__ int wsum[8];
    int tid = threadIdx.x;
    int lane = tid & 31, wid = tid >> 5;
    int base = blockIdx.x * 1024 + tid * 4;
    int v[4];
#pragma unroll
    for (int j = 0; j < 4; j++)
        v[j] = (base + j < ntot) ? g_cnt[base + j] : 0;
    int local = v[0] + v[1] + v[2] + v[3];
    int x = local;
#pragma unroll
    for (int o = 1; o < 32; o <<= 1) {
        int t = __shfl_up_sync(0xffffffffu, x, o);
        if (lane >= o) x += t;
    }
    if (lane == 31) wsum[wid] = x;
    __syncthreads();
    if (tid == 0) {
        int run = 0;
#pragma unroll
        for (int w = 0; w < 8; w++) { int t = wsum[w]; wsum[w] = run; run += t; }
        g_bsum[blockIdx.x] = run;
    }
    __syncthreads();
    int run = wsum[wid] + (x - local);
#pragma unroll
    for (int j = 0; j < 4; j++) {
        if (base + j < ntot) g_scan[base + j] = run;
        run += v[j];
    }
}

__global__ __launch_bounds__(256)
void scan2_kernel(int nb) {
    __shared__ int wsum[8];
    int tid = threadIdx.x;
    int lane = tid & 31, wid = tid >> 5;
    int val = (tid < nb) ? g_bsum[tid] : 0;
    int x = val;
#pragma unroll
    for (int o = 1; o < 32; o <<= 1) {
        int t = __shfl_up_sync(0xffffffffu, x, o);
        if (lane >= o) x += t;
    }
    if (lane == 31) wsum[wid] = x;
    __syncthreads();
    if (tid == 0) {
        int run = 0;
#pragma unroll
        for (int w = 0; w < 8; w++) { int t = wsum[w]; wsum[w] = run; run += t; }
    }
    __syncthreads();
    int excl = wsum[wid] + (x - val);
    if (tid < nb) g_bsum[tid] = excl;
}

__global__ void scan3_kernel(int ntot) {
    int i = blockIdx.x * blockDim.x + threadIdx.x;
    if (i >= ntot) return;
    int off = g_scan[i] + g_bsum[i >> 10];
    g_off[i] = off;
    g_cur[i] = off;
}

// ------------------------- scatter src ids into dst buckets ------------------
__global__ void scatter_kernel(const int* __restrict__ ps, const int* __restrict__ pd,
                               const int* __restrict__ ns, const int* __restrict__ nd,
                               int e) {
    int i = blockIdx.x * blockDim.x + threadIdx.x;
    if (i >= 2 * e) return;
    int sign = (i >= e);
    int j = sign ? i - e : i;
    int s = sign ? ns[j] : ps[j];
    int d = sign ? nd[j] : pd[j];
    int pos = atomicAdd(&g_cur[sign * NNODES + d], 1);
    g_srcs[pos] = s;
}

// ------------------------- CSR aggregation (warp per sign-node) --------------
__global__ __launch_bounds__(256)
void aggregate_kernel(float* __restrict__ out,
                      const float* __restrict__ b_pos,
                      const float* __restrict__ b_neg, int n) {
    int gw = (blockIdx.x * blockDim.x + threadIdx.x) >> 5;
    int lane = threadIdx.x & 31;
    if (gw >= 2 * n) return;
    int sign = (gw >= n);
    int d = sign ? gw - n : gw;
    int seg = sign * NNODES + d;
    int h = lane >> 2;

    float er_h = g_er[(size_t)sign * NNODES * HEADS + (size_t)d * HEADS + h];
    const float* elb = g_el + (size_t)sign * NNODES * HEADS;
    const __half* fb = g_feat16 + (size_t)sign * NNODES * HIDDEN;

    int start = g_off[seg];
    int end   = start + g_cnt[seg];

    float4 acc = make_float4(0.f, 0.f, 0.f, 0.f);
    float den = 0.f;

    int k = start;
    for (; k + 1 < end; k += 2) {
        int s0 = g_srcs[k];
        int s1 = g_srcs[k + 1];
        float eh0 = elb[(size_t)s0 * HEADS + h] + er_h;
        float eh1 = elb[(size_t)s1 * HEADS + h] + er_h;
        __half2 a0 = *(const __half2*)&fb[(size_t)s0 * HIDDEN + lane * 4];
        __half2 a1 = *(const __half2*)&fb[(size_t)s0 * HIDDEN + lane * 4 + 2];
        __half2 b0 = *(const __half2*)&fb[(size_t)s1 * HIDDEN + lane * 4];
        __half2 b1 = *(const __half2*)&fb[(size_t)s1 * HIDDEN + lane * 4 + 2];
        eh0 = (eh0 > 0.f) ? eh0 : NEG_SLOPE * eh0;
        eh1 = (eh1 > 0.f) ? eh1 : NEG_SLOPE * eh1;
        float ex0 = __expf(eh0);
        float ex1 = __expf(eh1);
        den += ex0 + ex1;
        float2 f0a = __half22float2(a0), f0b = __half22float2(a1);
        float2 f1a = __half22float2(b0), f1b = __half22float2(b1);
        acc.x = fmaf(ex0, f0a.x, fmaf(ex1, f1a.x, acc.x));
        acc.y = fmaf(ex0, f0a.y, fmaf(ex1, f1a.y, acc.y));
        acc.z = fmaf(ex0, f0b.x, fmaf(ex1, f1b.x, acc.z));
        acc.w = fmaf(ex0, f0b.y, fmaf(ex1, f1b.y, acc.w));
    }
    if (k < end) {
        int s = g_srcs[k];
        float eh = elb[(size_t)s * HEADS + h] + er_h;
        eh = (eh > 0.f) ? eh : NEG_SLOPE * eh;
        float ex = __expf(eh);
        den += ex;
        __half2 a0 = *(const __half2*)&fb[(size_t)s * HIDDEN + lane * 4];
        __half2 a1 = *(const __half2*)&fb[(size_t)s * HIDDEN + lane * 4 + 2];
        float2 fa = __half22float2(a0), fbv = __half22float2(a1);
        acc.x = fmaf(ex, fa.x, acc.x);
        acc.y = fmaf(ex, fa.y, acc.y);
        acc.z = fmaf(ex, fbv.x, acc.z);
        acc.w = fmaf(ex, fbv.y, acc.w);
    }
    float inv = (den > 0.f) ? (1.0f / den) : 0.0f;
    const float* bias = sign ? b_neg : b_pos;
    float4 bv = *(const float4*)(bias + lane * 4);
    float4 o = make_float4(acc.x * inv + bv.x, acc.y * inv + bv.y,
                           acc.z * inv + bv.z, acc.w * inv + bv.w);
    *(float4*)&out[((size_t)sign * n + d) * HIDDEN + lane * 4] = o;
}

// ------------------------- fp16 helpers --------------------------------------
__device__ __forceinline__ uint32_t f2h2(float lo, float hi) {
    __half2 h = __floats2half2_rn(lo, hi);
    return *(uint32_t*)&h;
}

#define MMA_F16(cr, a, b)                                                      \
    asm volatile("mma.sync.aligned.m16n8k16.row.col.f32.f16.f16.f32 "          \
                 "{%0,%1,%2,%3},{%4,%5,%6,%7},{%8,%9},{%0,%1,%2,%3};"          \
                 : "+f"((cr)[0]), "+f"((cr)[1]), "+f"((cr)[2]), "+f"((cr)[3])  \
                 : "r"((a)[0]), "r"((a)[1]), "r"((a)[2]), "r"((a)[3]),         \
                   "r"((b)[0]), "r"((b)[1]))

// ------------------------- tensor-core fp16 GEMM (double-buffered) -----------
// C[M,NT] = act( [A0|A1][M,K] @ B[K,NT] + bias );  NT in {128, 64}; K in {128,256}.
// CTA tile 128 x NT, 8 warps (4x2), warp tile 32 x NT/2.
// fp32 inputs converted to fp16 at smem commit; fp32 accumulate.
// A smem: [m][k] half2-packed, row stride 12 u32 (banks distinct for 8 rows).
// B smem: [k/2][n] half2-pairs (adjacent k interleaved), row stride NT+8 u32.
// One m16n8k16 MMA stage per 16-k tile. HOUT: fp16 C. PAIR: grid.y pointer set.
template <int NT, bool PAIR, bool HOUT>
__global__ __launch_bounds__(256, 2)
void gemm_tc(const float* __restrict__ A0, const float* __restrict__ A1,
             int M, int K,
             const float* __restrict__ B0, const float* __restrict__ B1,
             const float* __restrict__ bias, int relu,
             void* __restrict__ C0, void* __restrict__ C1,
             const float* __restrict__ al0, const float* __restrict__ ar0,
             float* __restrict__ el0, float* __restrict__ er0,
             const float* __restrict__ al1, const float* __restrict__ ar1,
             float* __restrict__ el1, float* __restrict__ er1) {
    constexpr int ASTR = 12;         // u32 (half2) per A row; 12*m mod 32 distinct
    constexpr int BSTR = NT + 8;     // u32 per B k-pair row
    constexpr int WN   = NT / 2;
    constexpr int NJ   = WN / 8;
    constexpr int ASZ  = 128 * ASTR;
    constexpr int BSZ  = 8 * BSTR;

    __shared__ __align__(16) uint32_t As[2 * ASZ];
    __shared__ __align__(16) uint32_t Bs[2 * BSZ];

    const float* B  = B0;
    void*        C  = C0;
    const float* al = al0; const float* ar = ar0;
    float*       el = el0; float*       er = er0;
    if (PAIR && blockIdx.y == 1) {
        B = B1; C = C1; al = al1; ar = ar1; el = el1; er = er1;
    }

    const int tid  = threadIdx.x;
    const int wid  = tid >> 5;
    const int lane = tid & 31;
    const int g    = lane >> 2;
    const int tig  = lane & 3;
    const int wm   = wid & 3;
    const int wn   = wid >> 2;
    const int m0   = blockIdx.x * 128;

    float c[2][NJ][4];
#pragma unroll
    for (int mi = 0; mi < 2; mi++)
#pragma unroll
        for (int nj = 0; nj < NJ; nj++)
#pragma unroll
            for (int q = 0; q < 4; q++) c[mi][nj][q] = 0.0f;

    float4 pa[2];       // A: 128x16 fp32 = 512 float4, 2/thread
    float4 pb[2];       // B: k-even row / k-odd row float4 at (kp, n4)

#define LOAD_A(k0, i, dstv) do {                                               \
        int idx = tid + (i) * 256;                                             \
        int row = idx >> 2; int kk = (idx & 3) * 4;                            \
        int grow = m0 + row;                                                   \
        if (grow < M) {                                                        \
            int kg = (k0) + kk;                                                \
            const float* srcp = (kg < 128) ? (A0 + (size_t)grow * 128 + kg)    \
                                           : (A1 + (size_t)grow * 128 + (kg - 128)); \
            dstv = *(const float4*)srcp;                                       \
        } else dstv = make_float4(0.f, 0.f, 0.f, 0.f);                         \
    } while (0)
#define LOAD_B(k0) do {                                                        \
        if (NT == 128) {                                                       \
            int kp = tid >> 5, n4 = (tid & 31) * 4;                            \
            pb[0] = *(const float4*)(B + (size_t)((k0) + 2 * kp)     * NT + n4); \
            pb[1] = *(const float4*)(B + (size_t)((k0) + 2 * kp + 1) * NT + n4); \
        } else if (tid < 128) {                                                \
            int kp = tid >> 4, n4 = (tid & 15) * 4;                            \
            pb[0] = *(const float4*)(B + (size_t)((k0) + 2 * kp)     * NT + n4); \
            pb[1] = *(const float4*)(B + (size_t)((k0) + 2 * kp + 1) * NT + n4); \
        }                                                                      \
    } while (0)
#define COMMIT(p) do {                                                         \
        _Pragma("unroll")                                                      \
        for (int i = 0; i < 2; i++) {                                          \
            int idx = tid + i * 256;                                           \
            int row = idx >> 2; int kp0 = (idx & 3) * 2;                       \
            uint2 t = make_uint2(f2h2(pa[i].x, pa[i].y), f2h2(pa[i].z, pa[i].w)); \
            *(uint2*)&As[(p) * ASZ + row * ASTR + kp0] = t;                    \
        }                                                                      \
        if (NT == 128) {                                                       \
            int kp = tid >> 5, n4 = (tid & 31) * 4;                            \
            uint4 t = make_uint4(f2h2(pb[0].x, pb[1].x), f2h2(pb[0].y, pb[1].y), \
                                 f2h2(pb[0].z, pb[1].z), f2h2(pb[0].w, pb[1].w)); \
            *(uint4*)&Bs[(p) * BSZ + kp * BSTR + n4] = t;                      \
        } else if (tid < 128) {                                                \
            int kp = tid >> 4, n4 = (tid & 15) * 4;                            \
            uint4 t = make_uint4(f2h2(pb[0].x, pb[1].x), f2h2(pb[0].y, pb[1].y), \
                                 f2h2(pb[0].z, pb[1].z), f2h2(pb[0].w, pb[1].w)); \
            *(uint4*)&Bs[(p) * BSZ + kp * BSTR + n4] = t;                      \
        }                                                                      \
    } while (0)

    // prologue
    LOAD_A(0, 0, pa[0]); LOAD_A(0, 1, pa[1]);
    LOAD_B(0);
    COMMIT(0);
    __syncthreads();
    if (K > 16) {
        LOAD_A(16, 0, pa[0]); LOAD_A(16, 1, pa[1]);
        LOAD_B(16);
    }

    int p = 0;
    for (int k0 = 0; k0 < K; k0 += 16) {
        if (k0 + 16 < K) {
            COMMIT(p ^ 1);
            if (k0 + 32 < K) {
                LOAD_A(k0 + 32, 0, pa[0]); LOAD_A(k0 + 32, 1, pa[1]);
                LOAD_B(k0 + 32);
            }
        }
        const uint32_t* Ap = &As[p * ASZ];
        const uint32_t* Bp = &Bs[p * BSZ];
        uint32_t af[2][4];
#pragma unroll
        for (int mi = 0; mi < 2; mi++) {
            int mb = wm * 32 + mi * 16;
            af[mi][0] = Ap[(mb + g)     * ASTR + tig];
            af[mi][1] = Ap[(mb + 8 + g) * ASTR + tig];
            af[mi][2] = Ap[(mb + g)     * ASTR + tig + 4];
            af[mi][3] = Ap[(mb + 8 + g) * ASTR + tig + 4];
        }
        uint32_t bf[NJ][2];
#pragma unroll
        for (int nj = 0; nj < NJ; nj++) {
            int nb = wn * WN + nj * 8;
            bf[nj][0] = Bp[tig       * BSTR + nb + g];
            bf[nj][1] = Bp[(tig + 4) * BSTR + nb + g];
        }
#pragma unroll
        for (int mi = 0; mi < 2; mi++)
#pragma unroll
            for (int nj = 0; nj < NJ; nj++)
                MMA_F16(c[mi][nj], af[mi], bf[nj]);
        __syncthreads();
        p ^= 1;
    }
#undef LOAD_A
#undef LOAD_B
#undef COMMIT

    // ---- fused el/er epilogue (NT=128 path only) ----
    if (NT == 128 && el != nullptr) {
#pragma unroll
        for (int mi = 0; mi < 2; mi++) {
#pragma unroll
            for (int h = 0; h < 4; h++) {
                float e0 = 0.f, e1 = 0.f, r0v = 0.f, r1v = 0.f;
#pragma unroll
                for (int q = 0; q < 2; q++) {
                    int nj = 2 * h + q;
                    int col = wn * 64 + nj * 8 + 2 * tig;
                    float a0 = al[col], a1 = al[col + 1];
                    float b0 = ar[col], b1 = ar[col + 1];
                    e0  += c[mi][nj][0] * a0 + c[mi][nj][1] * a1;
                    e1  += c[mi][nj][2] * a0 + c[mi][nj][3] * a1;
                    r0v += c[mi][nj][0] * b0 + c[mi][nj][1] * b1;
                    r1v += c[mi][nj][2] * b0 + c[mi][nj][3] * b1;
                }
                e0  += __shfl_xor_sync(0xffffffffu, e0, 1);
                e0  += __shfl_xor_sync(0xffffffffu, e0, 2);
                e1  += __shfl_xor_sync(0xffffffffu, e1, 1);
                e1  += __shfl_xor_sync(0xffffffffu, e1, 2);
                r0v += __shfl_xor_sync(0xffffffffu, r0v, 1);
                r0v += __shfl_xor_sync(0xffffffffu, r0v, 2);
                r1v += __shfl_xor_sync(0xffffffffu, r1v, 1);
                r1v += __shfl_xor_sync(0xffffffffu, r1v, 2);
                if (tig == 0) {
                    int hg = wn * 4 + h;
                    int ra = m0 + wm * 32 + mi * 16 + g;
                    int rb = ra + 8;
                    if (ra < M) { el[ra * HEADS + hg] = e0;  er[ra * HEADS + hg] = r0v; }
                    if (rb < M) { el[rb * HEADS + hg] = e1;  er[rb * HEADS + hg] = r1v; }
                }
            }
        }
    }

    // ---- store C with bias/relu (fp32 or fp16) ----
#pragma unroll
    for (int mi = 0; mi < 2; mi++) {
        int ra = m0 + wm * 32 + mi * 16 + g;
        int rb = ra + 8;
#pragma unroll
        for (int nj = 0; nj < NJ; nj++) {
            int col = wn * WN + nj * 8 + 2 * tig;
            float bx = 0.f, by = 0.f;
            if (bias) { bx = bias[col]; by = bias[col + 1]; }
            float v0 = c[mi][nj][0] + bx, v1 = c[mi][nj][1] + by;
            float v2 = c[mi][nj][2] + bx, v3 = c[mi][nj][3] + by;
            if (relu) {
                v0 = fmaxf(v0, 0.f); v1 = fmaxf(v1, 0.f);
                v2 = fmaxf(v2, 0.f); v3 = fmaxf(v3, 0.f);
            }
            if (HOUT) {
                __half* C16 = (__half*)C;
                if (ra < M) *(__half2*)&C16[(size_t)ra * NT + col] = __floats2half2_rn(v0, v1);
                if (rb < M) *(__half2*)&C16[(size_t)rb * NT + col] = __floats2half2_rn(v2, v3);
            } else {
                float* C32 = (float*)C;
                if (ra < M) *(float2*)&C32[(size_t)ra * NT + col] = make_float2(v0, v1);
                if (rb < M) *(float2*)&C32[(size_t)rb * NT + col] = make_float2(v2, v3);
            }
        }
    }
}

// ------------------------- launcher ------------------------------------------
extern "C" void kernel_launch(void* const* d_in, const int* in_sizes, int n_in,
                              void* d_out, int out_size) {
    const float* features = (const float*)d_in[0];
    const int*   pos_src  = (const int*)d_in[1];
    const int*   pos_dst  = (const int*)d_in[2];
    const int*   neg_src  = (const int*)d_in[3];
    const int*   neg_dst  = (const int*)d_in[4];
    const float* W_pos    = (const float*)d_in[5];
    const float* al_pos   = (const float*)d_in[6];
    const float* ar_pos   = (const float*)d_in[7];
    const float* b_pos    = (const float*)d_in[8];
    const float* W_neg    = (const float*)d_in[9];
    const float* al_neg   = (const float*)d_in[10];
    const float* ar_neg   = (const float*)d_in[11];
    const float* b_neg    = (const float*)d_in[12];
    const float* W1       = (const float*)d_in[13];
    const float* b1       = (const float*)d_in[14];
    const float* W2       = (const float*)d_in[15];
    const float* b2       = (const float*)d_in[16];
    float* out = (float*)d_out;

    int n = in_sizes[0] / HIDDEN;   // 100000
    int e = in_sizes[1];            // 600000

    void* p;
    cudaGetSymbolAddress(&p, g_feat16); __half* featp = (__half*)p;
    cudaGetSymbolAddress(&p, g_tmp);    float*  tmpp  = (float*)p;
    cudaGetSymbolAddress(&p, g_el);     float*  elp   = (float*)p;
    cudaGetSymbolAddress(&p, g_er);     float*  erp   = (float*)p;

    float* h_pos   = out;
    float* h_neg   = out + (size_t)n * HIDDEN;
    float* h_final = out + (size_t)2 * n * HIDDEN;

    int gb   = (n + 127) / 128;
    int nseg = 2 * n;
    int nb   = (nseg + 1023) / 1024;

    // Fork a side stream for the CSR build (independent of the feature GEMMs).
    cudaStream_t s1;
    cudaEvent_t ev_fork, ev_join;
    cudaStreamCreateWithFlags(&s1, cudaStreamNonBlocking);
    cudaEventCreateWithFlags(&ev_fork, cudaEventDisableTiming);
    cudaEventCreateWithFlags(&ev_join, cudaEventDisableTiming);

    cudaEventRecord(ev_fork, 0);
    cudaStreamWaitEvent(s1, ev_fork, 0);

    // --- side stream: CSR build ---
    init_cnt<<<(NSEG + 255) / 256, 256, 0, s1>>>();
    hist_kernel<<<(2 * e + 255) / 256, 256, 0, s1>>>(pos_dst, neg_dst, e);
    scan1_kernel<<<nb, 256, 0, s1>>>(nseg);
    scan2_kernel<<<1, 256, 0, s1>>>(nb);
    scan3_kernel<<<(nseg + 255) / 256, 256, 0, s1>>>(nseg);
    scatter_kernel<<<(2 * e + 255) / 256, 256, 0, s1>>>(pos_src, pos_dst, neg_src, neg_dst, e);
    cudaEventRecord(ev_join, s1);

    // --- main stream: feature transform GEMMs (fp16 MMA, both signs, fp16 out) ---
    {
        dim3 grid(gb, 2);
        gemm_tc<128, true, true><<<grid, 256>>>(
            features, features, n, HIDDEN,
            W_pos, W_neg, nullptr, 0,
            featp, featp + (size_t)NNODES * HIDDEN,
            al_pos, ar_pos, elp, erp,
            al_neg, ar_neg,
            elp + (size_t)NNODES * HEADS, erp + (size_t)NNODES * HEADS);
    }

    // join: aggregation needs both CSR and features
    cudaStreamWaitEvent(0, ev_join, 0);

    // --- fused softmax + aggregation + normalize + bias (h_pos | h_neg) ---
    {
        int gwb = (2 * n + 7) / 8;
        aggregate_kernel<<<gwb, 256>>>(out, b_pos, b_neg, n);
    }

    // --- MLP: h_final = relu([h_pos|h_neg] @ W1 + b1) @ W2 + b2 ---
    gemm_tc<128, false, false><<<gb, 256>>>(
        h_pos, h_neg, n, 2 * HIDDEN,
        W1, nullptr, b1, 1, tmpp, nullptr,
        nullptr, nullptr, nullptr, nullptr,
        nullptr, nullptr, nullptr, nullptr);
    gemm_tc<64, false, false><<<gb, 256>>>(
        tmpp, tmpp, n, HIDDEN,
        W2, nullptr, b2, 0, h_final, nullptr,
        nullptr, nullptr, nullptr, nullptr,
        nullptr, nullptr, nullptr, nullptr);
}

// round 11
// speedup vs baseline: 1.4697x; 1.1217x over previous
#include <cuda_runtime.h>
#include <cuda_fp16.h>
#include <cstdint>

#define NNODES 100000
#define NEDGES 600000
#define HIDDEN 128
#define HEADS  8
#define DH     16
#define NEG_SLOPE 0.2f
#define NSEG (2 * NNODES)            // (sign, node) segments

// ------------------------- scratch (static device globals) -------------------
__device__ __half g_feat16[2 * NNODES * HIDDEN]; // transformed features (fp16), per sign
__device__ float g_el  [2 * NNODES * HEADS];
__device__ float g_er  [2 * NNODES * HEADS];
__device__ int   g_cnt [NSEG];                  // per-(sign,node) in-degree
__device__ int   g_scan[NSEG];                  // block-local exclusive scan
__device__ int   g_off [NSEG];                  // global exclusive offsets
__device__ int   g_cur [NSEG];                  // scatter cursors
__device__ int   g_bsum[256];                   // per-block sums for scan
__device__ int   g_srcs[2 * NEDGES];            // src ids, dst-sorted

// ------------------------- init: cnt = 0 -------------------------------------
__global__ void init_cnt() {
    int i = blockIdx.x * blockDim.x + threadIdx.x;
    if (i < NSEG) g_cnt[i] = 0;
}

// ------------------------- histogram of dst ----------------------------------
__global__ void hist_kernel(const int* __restrict__ pd, const int* __restrict__ nd,
                            int e) {
    int i = blockIdx.x * blockDim.x + threadIdx.x;
    if (i >= 2 * e) return;
    int sign = (i >= e);
    int d = sign ? nd[i - e] : pd[i];
    atomicAdd(&g_cnt[sign * NNODES + d], 1);
}

// ------------------------- exclusive scan (3 kernels) ------------------------
__global__ __launch_bounds__(256)
void scan1_kernel(int ntot) {
    __shared__ int wsum[8];
    int tid = threadIdx.x;
    int lane = tid & 31, wid = tid >> 5;
    int base = blockIdx.x * 1024 + tid * 4;
    int v[4];
#pragma unroll
    for (int j = 0; j < 4; j++)
        v[j] = (base + j < ntot) ? g_cnt[base + j] : 0;
    int local = v[0] + v[1] + v[2] + v[3];
    int x = local;
#pragma unroll
    for (int o = 1; o < 32; o <<= 1) {
        int t = __shfl_up_sync(0xffffffffu, x, o);
        if (lane >= o) x += t;
    }
    if (lane == 31) wsum[wid] = x;
    __syncthreads();
    if (tid == 0) {
        int run = 0;
#pragma unroll
        for (int w = 0; w < 8; w++) { int t = wsum[w]; wsum[w] = run; run += t; }
        g_bsum[blockIdx.x] = run;
    }
    __syncthreads();
    int run = wsum[wid] + (x - local);
#pragma unroll
    for (int j = 0; j < 4; j++) {
        if (base + j < ntot) g_scan[base + j] = run;
        run += v[j];
    }
}

__global__ __launch_bounds__(256)
void scan2_kernel(int nb) {
    __shared__ int wsum[8];
    int tid = threadIdx.x;
    int lane = tid & 31, wid = tid >> 5;
    int val = (tid < nb) ? g_bsum[tid] : 0;
    int x = val;
#pragma unroll
    for (int o = 1; o < 32; o <<= 1) {
        int t = __shfl_up_sync(0xffffffffu, x, o);
        if (lane >= o) x += t;
    }
    if (lane == 31) wsum[wid] = x;
    __syncthreads();
    if (tid == 0) {
        int run = 0;
#pragma unroll
        for (int w = 0; w < 8; w++) { int t = wsum[w]; wsum[w] = run; run += t; }
    }
    __syncthreads();
    int excl = wsum[wid] + (x - val);
    if (tid < nb) g_bsum[tid] = excl;
}

__global__ void scan3_kernel(int ntot) {
    int i = blockIdx.x * blockDim.x + threadIdx.x;
    if (i >= ntot) return;
    int off = g_scan[i] + g_bsum[i >> 10];
    g_off[i] = off;
    g_cur[i] = off;
}

// ------------------------- scatter src ids into dst buckets ------------------
__global__ void scatter_kernel(const int* __restrict__ ps, const int* __restrict__ pd,
                               const int* __restrict__ ns, const int* __restrict__ nd,
                               int e) {
    int i = blockIdx.x * blockDim.x + threadIdx.x;
    if (i >= 2 * e) return;
    int sign = (i >= e);
    int j = sign ? i - e : i;
    int s = sign ? ns[j] : ps[j];
    int d = sign ? nd[j] : pd[j];
    int pos = atomicAdd(&g_cur[sign * NNODES + d], 1);
    g_srcs[pos] = s;
}

// ------------------------- CSR aggregation (warp per sign-node) --------------
__global__ __launch_bounds__(256)
void aggregate_kernel(float* __restrict__ out,
                      const float* __restrict__ b_pos,
                      const float* __restrict__ b_neg, int n) {
    int gw = (blockIdx.x * blockDim.x + threadIdx.x) >> 5;
    int lane = threadIdx.x & 31;
    if (gw >= 2 * n) return;
    int sign = (gw >= n);
    int d = sign ? gw - n : gw;
    int seg = sign * NNODES + d;
    int h = lane >> 2;

    float er_h = g_er[(size_t)sign * NNODES * HEADS + (size_t)d * HEADS + h];
    const float* elb = g_el + (size_t)sign * NNODES * HEADS;
    const __half* fb = g_feat16 + (size_t)sign * NNODES * HIDDEN;

    int start = g_off[seg];
    int end   = start + g_cnt[seg];

    float4 acc = make_float4(0.f, 0.f, 0.f, 0.f);
    float den = 0.f;

    int k = start;
    for (; k + 1 < end; k += 2) {
        int s0 = g_srcs[k];
        int s1 = g_srcs[k + 1];
        float eh0 = elb[(size_t)s0 * HEADS + h] + er_h;
        float eh1 = elb[(size_t)s1 * HEADS + h] + er_h;
        __half2 a0 = *(const __half2*)&fb[(size_t)s0 * HIDDEN + lane * 4];
        __half2 a1 = *(const __half2*)&fb[(size_t)s0 * HIDDEN + lane * 4 + 2];
        __half2 b0 = *(const __half2*)&fb[(size_t)s1 * HIDDEN + lane * 4];
        __half2 b1 = *(const __half2*)&fb[(size_t)s1 * HIDDEN + lane * 4 + 2];
        eh0 = (eh0 > 0.f) ? eh0 : NEG_SLOPE * eh0;
        eh1 = (eh1 > 0.f) ? eh1 : NEG_SLOPE * eh1;
        float ex0 = __expf(eh0);
        float ex1 = __expf(eh1);
        den += ex0 + ex1;
        float2 f0a = __half22float2(a0), f0b = __half22float2(a1);
        float2 f1a = __half22float2(b0), f1b = __half22float2(b1);
        acc.x = fmaf(ex0, f0a.x, fmaf(ex1, f1a.x, acc.x));
        acc.y = fmaf(ex0, f0a.y, fmaf(ex1, f1a.y, acc.y));
        acc.z = fmaf(ex0, f0b.x, fmaf(ex1, f1b.x, acc.z));
        acc.w = fmaf(ex0, f0b.y, fmaf(ex1, f1b.y, acc.w));
    }
    if (k < end) {
        int s = g_srcs[k];
        float eh = elb[(size_t)s * HEADS + h] + er_h;
        eh = (eh > 0.f) ? eh : NEG_SLOPE * eh;
        float ex = __expf(eh);
        den += ex;
        __half2 a0 = *(const __half2*)&fb[(size_t)s * HIDDEN + lane * 4];
        __half2 a1 = *(const __half2*)&fb[(size_t)s * HIDDEN + lane * 4 + 2];
        float2 fa = __half22float2(a0), fbv = __half22float2(a1);
        acc.x = fmaf(ex, fa.x, acc.x);
        acc.y = fmaf(ex, fa.y, acc.y);
        acc.z = fmaf(ex, fbv.x, acc.z);
        acc.w = fmaf(ex, fbv.y, acc.w);
    }
    float inv = (den > 0.f) ? (1.0f / den) : 0.0f;
    const float* bias = sign ? b_neg : b_pos;
    float4 bv = *(const float4*)(bias + lane * 4);
    float4 o = make_float4(acc.x * inv + bv.x, acc.y * inv + bv.y,
                           acc.z * inv + bv.z, acc.w * inv + bv.w);
    *(float4*)&out[((size_t)sign * n + d) * HIDDEN + lane * 4] = o;
}

// ------------------------- fp16 helpers --------------------------------------
__device__ __forceinline__ uint32_t f2h2(float lo, float hi) {
    __half2 h = __floats2half2_rn(lo, hi);
    return *(uint32_t*)&h;
}

#define MMA_F16(cr, a, b)                                                      \
    asm volatile("mma.sync.aligned.m16n8k16.row.col.f32.f16.f16.f32 "          \
                 "{%0,%1,%2,%3},{%4,%5,%6,%7},{%8,%9},{%0,%1,%2,%3};"          \
                 : "+f"((cr)[0]), "+f"((cr)[1]), "+f"((cr)[2]), "+f"((cr)[3])  \
                 : "r"((a)[0]), "r"((a)[1]), "r"((a)[2]), "r"((a)[3]),         \
                   "r"((b)[0]), "r"((b)[1]))

// ------------------------- tensor-core fp16 GEMM (feature pass) --------------
// Same as R10: CTA tile 128 x 128, 8 warps (4x2), double-buffered,
// fused el/er epilogue, fp16 C, grid.y selects pos/neg pointer set.
__global__ __launch_bounds__(256, 2)
void gemm_feat(const float* __restrict__ A0, int M, int K,
               const float* __restrict__ B0, const float* __restrict__ B1,
               __half* __restrict__ C0, __half* __restrict__ C1,
               const float* __restrict__ al0, const float* __restrict__ ar0,
               float* __restrict__ el0, float* __restrict__ er0,
               const float* __restrict__ al1, const float* __restrict__ ar1,
               float* __restrict__ el1, float* __restrict__ er1) {
    constexpr int NT = 128;
    constexpr int ASTR = 12;
    constexpr int BSTR = NT + 8;
    constexpr int WN   = NT / 2;
    constexpr int NJ   = WN / 8;
    constexpr int ASZ  = 128 * ASTR;
    constexpr int BSZ  = 8 * BSTR;

    __shared__ __align__(16) uint32_t As[2 * ASZ];
    __shared__ __align__(16) uint32_t Bs[2 * BSZ];

    const float* B  = B0;
    __half*      C  = C0;
    const float* al = al0; const float* ar = ar0;
    float*       el = el0; float*       er = er0;
    if (blockIdx.y == 1) { B = B1; C = C1; al = al1; ar = ar1; el = el1; er = er1; }

    const int tid  = threadIdx.x;
    const int wid  = tid >> 5;
    const int lane = tid & 31;
    const int g    = lane >> 2;
    const int tig  = lane & 3;
    const int wm   = wid & 3;
    const int wn   = wid >> 2;
    const int m0   = blockIdx.x * 128;

    float c[2][NJ][4];
#pragma unroll
    for (int mi = 0; mi < 2; mi++)
#pragma unroll
        for (int nj = 0; nj < NJ; nj++)
#pragma unroll
            for (int q = 0; q < 4; q++) c[mi][nj][q] = 0.0f;

    float4 pa[2], pb[2];

#define LOAD_A(k0, i, dstv) do {                                               \
        int idx = tid + (i) * 256;                                             \
        int row = idx >> 2; int kk = (idx & 3) * 4;                            \
        int grow = m0 + row;                                                   \
        if (grow < M) {                                                        \
            dstv = *(const float4*)(A0 + (size_t)grow * 128 + (k0) + kk);      \
        } else dstv = make_float4(0.f, 0.f, 0.f, 0.f);                         \
    } while (0)
#define LOAD_B(k0) do {                                                        \
        int kp = tid >> 5, n4 = (tid & 31) * 4;                                \
        pb[0] = *(const float4*)(B + (size_t)((k0) + 2 * kp)     * NT + n4);   \
        pb[1] = *(const float4*)(B + (size_t)((k0) + 2 * kp + 1) * NT + n4);   \
    } while (0)
#define COMMIT(p) do {                                                         \
        _Pragma("unroll")                                                      \
        for (int i = 0; i < 2; i++) {                                          \
            int idx = tid + i * 256;                                           \
            int row = idx >> 2; int kp0 = (idx & 3) * 2;                       \
            uint2 t = make_uint2(f2h2(pa[i].x, pa[i].y), f2h2(pa[i].z, pa[i].w)); \
            *(uint2*)&As[(p) * ASZ + row * ASTR + kp0] = t;                    \
        }                                                                      \
        {                                                                      \
            int kp = tid >> 5, n4 = (tid & 31) * 4;                            \
            uint4 t = make_uint4(f2h2(pb[0].x, pb[1].x), f2h2(pb[0].y, pb[1].y), \
                                 f2h2(pb[0].z, pb[1].z), f2h2(pb[0].w, pb[1].w)); \
            *(uint4*)&Bs[(p) * BSZ + kp * BSTR + n4] = t;                      \
        }                                                                      \
    } while (0)

    LOAD_A(0, 0, pa[0]); LOAD_A(0, 1, pa[1]);
    LOAD_B(0);
    COMMIT(0);
    __syncthreads();
    if (K > 16) {
        LOAD_A(16, 0, pa[0]); LOAD_A(16, 1, pa[1]);
        LOAD_B(16);
    }

    int p = 0;
    for (int k0 = 0; k0 < K; k0 += 16) {
        if (k0 + 16 < K) {
            COMMIT(p ^ 1);
            if (k0 + 32 < K) {
                LOAD_A(k0 + 32, 0, pa[0]); LOAD_A(k0 + 32, 1, pa[1]);
                LOAD_B(k0 + 32);
            }
        }
        const uint32_t* Ap = &As[p * ASZ];
        const uint32_t* Bp = &Bs[p * BSZ];
        uint32_t af[2][4];
#pragma unroll
        for (int mi = 0; mi < 2; mi++) {
            int mb = wm * 32 + mi * 16;
            af[mi][0] = Ap[(mb + g)     * ASTR + tig];
            af[mi][1] = Ap[(mb + 8 + g) * ASTR + tig];
            af[mi][2] = Ap[(mb + g)     * ASTR + tig + 4];
            af[mi][3] = Ap[(mb + 8 + g) * ASTR + tig + 4];
        }
        uint32_t bf[NJ][2];
#pragma unroll
        for (int nj = 0; nj < NJ; nj++) {
            int nb = wn * WN + nj * 8;
            bf[nj][0] = Bp[tig       * BSTR + nb + g];
            bf[nj][1] = Bp[(tig + 4) * BSTR + nb + g];
        }
#pragma unroll
        for (int mi = 0; mi < 2; mi++)
#pragma unroll
            for (int nj = 0; nj < NJ; nj++)
                MMA_F16(c[mi][nj], af[mi], bf[nj]);
        __syncthreads();
        p ^= 1;
    }
#undef LOAD_A
#undef LOAD_B
#undef COMMIT

    // ---- fused el/er epilogue ----
#pragma unroll
    for (int mi = 0; mi < 2; mi++) {
#pragma unroll
        for (int h = 0; h < 4; h++) {
            float e0 = 0.f, e1 = 0.f, r0v = 0.f, r1v = 0.f;
#pragma unroll
            for (int q = 0; q < 2; q++) {
                int nj = 2 * h + q;
                int col = wn * 64 + nj * 8 + 2 * tig;
                float a0 = al[col], a1 = al[col + 1];
                float b0 = ar[col], b1 = ar[col + 1];
                e0  += c[mi][nj][0] * a0 + c[mi][nj][1] * a1;
                e1  += c[mi][nj][2] * a0 + c[mi][nj][3] * a1;
                r0v += c[mi][nj][0] * b0 + c[mi][nj][1] * b1;
                r1v += c[mi][nj][2] * b0 + c[mi][nj][3] * b1;
            }
            e0  += __shfl_xor_sync(0xffffffffu, e0, 1);
            e0  += __shfl_xor_sync(0xffffffffu, e0, 2);
            e1  += __shfl_xor_sync(0xffffffffu, e1, 1);
            e1  += __shfl_xor_sync(0xffffffffu, e1, 2);
            r0v += __shfl_xor_sync(0xffffffffu, r0v, 1);
            r0v += __shfl_xor_sync(0xffffffffu, r0v, 2);
            r1v += __shfl_xor_sync(0xffffffffu, r1v, 1);
            r1v += __shfl_xor_sync(0xffffffffu, r1v, 2);
            if (tig == 0) {
                int hg = wn * 4 + h;
                int ra = m0 + wm * 32 + mi * 16 + g;
                int rb = ra + 8;
                if (ra < M) { el[ra * HEADS + hg] = e0;  er[ra * HEADS + hg] = r0v; }
                if (rb < M) { el[rb * HEADS + hg] = e1;  er[rb * HEADS + hg] = r1v; }
            }
        }
    }

    // ---- store C (fp16) ----
#pragma unroll
    for (int mi = 0; mi < 2; mi++) {
        int ra = m0 + wm * 32 + mi * 16 + g;
        int rb = ra + 8;
#pragma unroll
        for (int nj = 0; nj < NJ; nj++) {
            int col = wn * WN + nj * 8 + 2 * tig;
            if (ra < M) *(__half2*)&C[(size_t)ra * NT + col] =
                __floats2half2_rn(c[mi][nj][0], c[mi][nj][1]);
            if (rb < M) *(__half2*)&C[(size_t)rb * NT + col] =
                __floats2half2_rn(c[mi][nj][2], c[mi][nj][3]);
        }
    }
}

// ------------------------- fused MLP kernel ----------------------------------
// h_final[M,64] = relu([h_pos|h_neg][M,256] @ W1[256,128] + b1) @ W2[128,64] + b2
// Stage 1: 128x128 tile GEMM (K=256) as in gemm_feat (A0=h_pos rows, A1=h_neg).
// Stage 2: hidden tile -> smem fp16 (XOR swizzle), W2 -> smem fp16, 8 more
// k16 MMA steps, store fp32. No global roundtrip for the hidden activation.
__global__ __launch_bounds__(256, 2)
void mlp_fused(const float* __restrict__ A0, const float* __restrict__ A1,
               int M,
               const float* __restrict__ W1, const float* __restrict__ b1,
               const float* __restrict__ W2, const float* __restrict__ b2,
               float* __restrict__ outF) {
    constexpr int NT = 128;
    constexpr int ASTR = 12;
    constexpr int BSTR = NT + 8;
    constexpr int NJ   = 8;
    constexpr int ASZ  = 128 * ASTR;   // 1536
    constexpr int BSZ  = 8 * BSTR;     // 1088
    // union: stage1 (2*ASZ + 2*BSZ = 5248) vs stage2 (Hs 8192 + B2s 4096 = 12288)
    __shared__ __align__(16) uint32_t smem[12288];
    uint32_t* As  = smem;
    uint32_t* Bs  = smem + 2 * ASZ;
    uint32_t* Hs  = smem;              // [128 rows][64 kpairs], swizzled
    uint32_t* B2s = smem + 8192;       // [64 kpairs][64 n], swizzled

    const int tid  = threadIdx.x;
    const int wid  = tid >> 5;
    const int lane = tid & 31;
    const int g    = lane >> 2;
    const int tig  = lane & 3;
    const int wm   = wid & 3;
    const int wn   = wid >> 2;
    const int m0   = blockIdx.x * 128;

    float c[2][NJ][4];
#pragma unroll
    for (int mi = 0; mi < 2; mi++)
#pragma unroll
        for (int nj = 0; nj < NJ; nj++)
#pragma unroll
            for (int q = 0; q < 4; q++) c[mi][nj][q] = 0.0f;

    float4 pa[2], pb[2];

#define LOAD_A(k0, i, dstv) do {                                               \
        int idx = tid + (i) * 256;                                             \
        int row = idx >> 2; int kk = (idx & 3) * 4;                            \
        int grow = m0 + row;                                                   \
        if (grow < M) {                                                        \
            int kg = (k0) + kk;                                                \
            const float* srcp = (kg < 128) ? (A0 + (size_t)grow * 128 + kg)    \
                                           : (A1 + (size_t)grow * 128 + (kg - 128)); \
            dstv = *(const float4*)srcp;                                       \
        } else dstv = make_float4(0.f, 0.f, 0.f, 0.f);                         \
    } while (0)
#define LOAD_B(k0) do {                                                        \
        int kp = tid >> 5, n4 = (tid & 31) * 4;                                \
        pb[0] = *(const float4*)(W1 + (size_t)((k0) + 2 * kp)     * NT + n4);  \
        pb[1] = *(const float4*)(W1 + (size_t)((k0) + 2 * kp + 1) * NT + n4);  \
    } while (0)
#define COMMIT(p) do {                                                         \
        _Pragma("unroll")                                                      \
        for (int i = 0; i < 2; i++) {                                          \
            int idx = tid + i * 256;                                           \
            int row = idx >> 2; int kp0 = (idx & 3) * 2;                       \
            uint2 t = make_uint2(f2h2(pa[i].x, pa[i].y), f2h2(pa[i].z, pa[i].w)); \
            *(uint2*)&As[(p) * ASZ + row * ASTR + kp0] = t;                    \
        }                                                                      \
        {                                                                      \
            int kp = tid >> 5, n4 = (tid & 31) * 4;                            \
            uint4 t = make_uint4(f2h2(pb[0].x, pb[1].x), f2h2(pb[0].y, pb[1].y), \
                                 f2h2(pb[0].z, pb[1].z), f2h2(pb[0].w, pb[1].w)); \
            *(uint4*)&Bs[(p) * BSZ + kp * BSTR + n4] = t;                      \
        }                                                                      \
    } while (0)

    // ---- stage 1: K=256 ----
    LOAD_A(0, 0, pa[0]); LOAD_A(0, 1, pa[1]);
    LOAD_B(0);
    COMMIT(0);
    __syncthreads();
    LOAD_A(16, 0, pa[0]); LOAD_A(16, 1, pa[1]);
    LOAD_B(16);

    int p = 0;
    for (int k0 = 0; k0 < 256; k0 += 16) {
        if (k0 + 16 < 256) {
            COMMIT(p ^ 1);
            if (k0 + 32 < 256) {
                LOAD_A(k0 + 32, 0, pa[0]); LOAD_A(k0 + 32, 1, pa[1]);
                LOAD_B(k0 + 32);
            }
        }
        const uint32_t* Ap = &As[p * ASZ];
        const uint32_t* Bp = &Bs[p * BSZ];
        uint32_t af[2][4];
#pragma unroll
        for (int mi = 0; mi < 2; mi++) {
            int mb = wm * 32 + mi * 16;
            af[mi][0] = Ap[(mb + g)     * ASTR + tig];
            af[mi][1] = Ap[(mb + 8 + g) * ASTR + tig];
            af[mi][2] = Ap[(mb + g)     * ASTR + tig + 4];
            af[mi][3] = Ap[(mb + 8 + g) * ASTR + tig + 4];
        }
        uint32_t bf[NJ][2];
#pragma unroll
        for (int nj = 0; nj < NJ; nj++) {
            int nb = wn * 64 + nj * 8;
            bf[nj][0] = Bp[tig       * BSTR + nb + g];
            bf[nj][1] = Bp[(tig + 4) * BSTR + nb + g];
        }
#pragma unroll
        for (int mi = 0; mi < 2; mi++)
#pragma unroll
            for (int nj = 0; nj < NJ; nj++)
                MMA_F16(c[mi][nj], af[mi], bf[nj]);
        __syncthreads();
        p ^= 1;
    }
#undef LOAD_A
#undef LOAD_B
#undef COMMIT
    // last loop iteration ended with __syncthreads: stage-1 smem free now.

    // ---- write hidden (bias + relu, fp16) into Hs, swizzle kp ^ ((m&7)<<2) ----
#pragma unroll
    for (int mi = 0; mi < 2; mi++) {
        int ra = wm * 32 + mi * 16 + g;      // local rows
        int rb = ra + 8;
#pragma unroll
        for (int nj = 0; nj < NJ; nj++) {
            int col = wn * 64 + nj * 8 + 2 * tig;
            float bx = b1[col], by = b1[col + 1];
            float v0 = fmaxf(c[mi][nj][0] + bx, 0.f);
            float v1 = fmaxf(c[mi][nj][1] + by, 0.f);
            float v2 = fmaxf(c[mi][nj][2] + bx, 0.f);
            float v3 = fmaxf(c[mi][nj][3] + by, 0.f);
            int cp = wn * 32 + nj * 4 + tig;  // u32 (kpair) column
            Hs[ra * 64 + (cp ^ (g << 2))] = f2h2(v0, v1);
            Hs[rb * 64 + (cp ^ (g << 2))] = f2h2(v2, v3);
        }
    }

    // ---- load W2 [128,64] into B2s, swizzle n ^ ((kp&3)<<3) ----
#pragma unroll
    for (int i = 0; i < 4; i++) {
        int idx = tid + i * 256;             // 0..1023
        int kp = idx >> 4;                   // 0..63
        int n4 = (idx & 15) * 4;             // 0..60
        float4 ev = *(const float4*)(W2 + (size_t)(2 * kp)     * 64 + n4);
        float4 ov = *(const float4*)(W2 + (size_t)(2 * kp + 1) * 64 + n4);
        uint4 t = make_uint4(f2h2(ev.x, ov.x), f2h2(ev.y, ov.y),
                             f2h2(ev.z, ov.z), f2h2(ev.w, ov.w));
        *(uint4*)&B2s[kp * 64 + (n4 ^ ((kp & 3) << 3))] = t;
    }
    __syncthreads();

    // ---- stage 2: [128,128] @ [128,64], 8 k16 steps ----
    float c2[2][4][4];
#pragma unroll
    for (int mi = 0; mi < 2; mi++)
#pragma unroll
        for (int nj = 0; nj < 4; nj++)
#pragma unroll
            for (int q = 0; q < 4; q++) c2[mi][nj][q] = 0.0f;

#pragma unroll
    for (int ks8 = 0; ks8 < 8; ks8++) {
        int kp0 = ks8 * 8;
        uint32_t af[2][4];
#pragma unroll
        for (int mi = 0; mi < 2; mi++) {
            int mb = wm * 32 + mi * 16;
            af[mi][0] = Hs[(mb + g)     * 64 + ((kp0 + tig)     ^ (g << 2))];
            af[mi][1] = Hs[(mb + 8 + g) * 64 + ((kp0 + tig)     ^ (g << 2))];
            af[mi][2] = Hs[(mb + g)     * 64 + ((kp0 + tig + 4) ^ (g << 2))];
            af[mi][3] = Hs[(mb + 8 + g) * 64 + ((kp0 + tig + 4) ^ (g << 2))];
        }
        uint32_t bf[4][2];
#pragma unroll
        for (int nj = 0; nj < 4; nj++) {
            int nb = wn * 32 + nj * 8 + g;
            bf[nj][0] = B2s[(kp0 + tig)     * 64 + (nb ^ (tig << 3))];
            bf[nj][1] = B2s[(kp0 + tig + 4) * 64 + (nb ^ (tig << 3))];
        }
#pragma unroll
        for (int mi = 0; mi < 2; mi++)
#pragma unroll
            for (int nj = 0; nj < 4; nj++)
                MMA_F16(c2[mi][nj], af[mi], bf[nj]);
    }

    // ---- store h_final (fp32, + b2) ----
#pragma unroll
    for (int mi = 0; mi < 2; mi++) {
        int ra = m0 + wm * 32 + mi * 16 + g;
        int rb = ra + 8;
#pragma unroll
        for (int nj = 0; nj < 4; nj++) {
            int col = wn * 32 + nj * 8 + 2 * tig;
            float bx = b2[col], by = b2[col + 1];
            if (ra < M) *(float2*)&outF[(size_t)ra * 64 + col] =
                make_float2(c2[mi][nj][0] + bx, c2[mi][nj][1] + by);
            if (rb < M) *(float2*)&outF[(size_t)rb * 64 + col] =
                make_float2(c2[mi][nj][2] + bx, c2[mi][nj][3] + by);
        }
    }
}

// ------------------------- launcher ------------------------------------------
extern "C" void kernel_launch(void* const* d_in, const int* in_sizes, int n_in,
                              void* d_out, int out_size) {
    const float* features = (const float*)d_in[0];
    const int*   pos_src  = (const int*)d_in[1];
    const int*   pos_dst  = (const int*)d_in[2];
    const int*   neg_src  = (const int*)d_in[3];
    const int*   neg_dst  = (const int*)d_in[4];
    const float* W_pos    = (const float*)d_in[5];
    const float* al_pos   = (const float*)d_in[6];
    const float* ar_pos   = (const float*)d_in[7];
    const float* b_pos    = (const float*)d_in[8];
    const float* W_neg    = (const float*)d_in[9];
    const float* al_neg   = (const float*)d_in[10];
    const float* ar_neg   = (const float*)d_in[11];
    const float* b_neg    = (const float*)d_in[12];
    const float* W1       = (const float*)d_in[13];
    const float* b1       = (const float*)d_in[14];
    const float* W2       = (const float*)d_in[15];
    const float* b2       = (const float*)d_in[16];
    float* out = (float*)d_out;

    int n = in_sizes[0] / HIDDEN;   // 100000
    int e = in_sizes[1];            // 600000

    void* p;
    cudaGetSymbolAddress(&p, g_feat16); __half* featp = (__half*)p;
    cudaGetSymbolAddress(&p, g_el);     float*  elp   = (float*)p;
    cudaGetSymbolAddress(&p, g_er);     float*  erp   = (float*)p;

    float* h_pos   = out;
    float* h_neg   = out + (size_t)n * HIDDEN;
    float* h_final = out + (size_t)2 * n * HIDDEN;

    int gb   = (n + 127) / 128;
    int nseg = 2 * n;
    int nb   = (nseg + 1023) / 1024;

    // Fork a side stream for the CSR build (independent of the feature GEMMs).
    cudaStream_t s1;
    cudaEvent_t ev_fork, ev_join;
    cudaStreamCreateWithFlags(&s1, cudaStreamNonBlocking);
    cudaEventCreateWithFlags(&ev_fork, cudaEventDisableTiming);
    cudaEventCreateWithFlags(&ev_join, cudaEventDisableTiming);

    cudaEventRecord(ev_fork, 0);
    cudaStreamWaitEvent(s1, ev_fork, 0);

    // --- side stream: CSR build ---
    init_cnt<<<(NSEG + 255) / 256, 256, 0, s1>>>();
    hist_kernel<<<(2 * e + 255) / 256, 256, 0, s1>>>(pos_dst, neg_dst, e);
    scan1_kernel<<<nb, 256, 0, s1>>>(nseg);
    scan2_kernel<<<1, 256, 0, s1>>>(nb);
    scan3_kernel<<<(nseg + 255) / 256, 256, 0, s1>>>(nseg);
    scatter_kernel<<<(2 * e + 255) / 256, 256, 0, s1>>>(pos_src, pos_dst, neg_src, neg_dst, e);
    cudaEventRecord(ev_join, s1);

    // --- main stream: feature transform GEMMs (fp16 MMA, both signs) ---
    {
        dim3 grid(gb, 2);
        gemm_feat<<<grid, 256>>>(
            features, n, HIDDEN,
            W_pos, W_neg,
            featp, featp + (size_t)NNODES * HIDDEN,
            al_pos, ar_pos, elp, erp,
            al_neg, ar_neg,
            elp + (size_t)NNODES * HEADS, erp + (size_t)NNODES * HEADS);
    }

    // join: aggregation needs both CSR and features
    cudaStreamWaitEvent(0, ev_join, 0);

    // --- fused softmax + aggregation + normalize + bias (h_pos | h_neg) ---
    {
        int gwb = (2 * n + 7) / 8;
        aggregate_kernel<<<gwb, 256>>>(out, b_pos, b_neg, n);
    }

    // --- fused MLP: h_final = relu([h_pos|h_neg] @ W1 + b1) @ W2 + b2 ---
    mlp_fused<<<gb, 256>>>(h_pos, h_neg, n, W1, b1, W2, b2, h_final);
}

// round 12
// speedup vs baseline: 1.5698x; 1.0681x over previous
#include <cuda_runtime.h>
#include <cuda_fp16.h>
#include <cstdint>

#define NNODES 100000
#define NEDGES 600000
#define HIDDEN 128
#define HEADS  8
#define DH     16
#define NEG_SLOPE 0.2f
#define NSEG (2 * NNODES)            // (sign, node) segments

// ------------------------- scratch (static device globals) -------------------
__device__ __half g_feat16[2 * NNODES * HIDDEN]; // transformed features (fp16), per sign
__device__ float g_el  [2 * NNODES * HEADS];
__device__ float g_er  [2 * NNODES * HEADS];
__device__ int   g_cnt [NSEG];                  // per-seg in-degree (self-zeroing)
__device__ int   g_off [NSEG];                  // segment start offsets
__device__ int   g_cur [NSEG];                  // scatter cursors (end after scatter)
__device__ int   g_total;                       // block-base allocator (self-zeroing)
__device__ int   g_srcs[2 * NEDGES];            // src ids, bucketed by (sign,dst)

// ------------------------- histogram of dst ----------------------------------
// g_cnt is all-zero on entry: zero-initialized at load, re-zeroed by scan_fused
// each replay (deterministic invariant).
__global__ void hist_kernel(const int* __restrict__ pd, const int* __restrict__ nd,
                            int e) {
    int i = blockIdx.x * blockDim.x + threadIdx.x;
    if (i >= 2 * e) return;
    int sign = (i >= e);
    int d = sign ? nd[i - e] : pd[i];
    atomicAdd(&g_cnt[sign * NNODES + d], 1);
}

// ------------------------- fused allocator scan ------------------------------
// Each block scans 1024 counters locally and claims a contiguous range via
// atomicAdd on g_total (bucket ranges need not be in segment order).
// Zeroes g_cnt after reading (next-replay init). g_total reset by scatter.
__global__ __launch_bounds__(256)
void scan_fused(int ntot) {
    __shared__ int wsum[8];
    __shared__ int sbase;
    int tid = threadIdx.x;
    int lane = tid & 31, wid = tid >> 5;
    int base = blockIdx.x * 1024 + tid * 4;
    int v[4];
#pragma unroll
    for (int j = 0; j < 4; j++) {
        v[j] = (base + j < ntot) ? g_cnt[base + j] : 0;
    }
#pragma unroll
    for (int j = 0; j < 4; j++)
        if (base + j < ntot) g_cnt[base + j] = 0;
    int local = v[0] + v[1] + v[2] + v[3];
    int x = local;
#pragma unroll
    for (int o = 1; o < 32; o <<= 1) {
        int t = __shfl_up_sync(0xffffffffu, x, o);
        if (lane >= o) x += t;
    }
    if (lane == 31) wsum[wid] = x;
    __syncthreads();
    if (tid == 0) {
        int run = 0;
#pragma unroll
        for (int w = 0; w < 8; w++) { int t = wsum[w]; wsum[w] = run; run += t; }
        sbase = atomicAdd(&g_total, run);
    }
    __syncthreads();
    int run = sbase + wsum[wid] + (x - local);
#pragma unroll
    for (int j = 0; j < 4; j++) {
        if (base + j < ntot) { g_off[base + j] = run; g_cur[base + j] = run; }
        run += v[j];
    }
}

// ------------------------- scatter src ids into buckets ----------------------
// Also resets g_total for the next replay (no reader of g_total here).
__global__ void scatter_kernel(const int* __restrict__ ps, const int* __restrict__ pd,
                               const int* __restrict__ ns, const int* __restrict__ nd,
                               int e) {
    int i = blockIdx.x * blockDim.x + threadIdx.x;
    if (i == 0) g_total = 0;
    if (i >= 2 * e) return;
    int sign = (i >= e);
    int j = sign ? i - e : i;
    int s = sign ? ns[j] : ps[j];
    int d = sign ? nd[j] : pd[j];
    int pos = atomicAdd(&g_cur[sign * NNODES + d], 1);
    g_srcs[pos] = s;
}

// ------------------------- CSR aggregation (half-warp per segment) -----------
// lanes 0-15 -> segment 2*warp, lanes 16-31 -> segment 2*warp+1.
// lane16 l owns dims [8l..8l+7] (one 16B uint4 of 8 halves); head = l/2.
// Segment end comes from post-scatter cursor g_cur (== off + cnt).
__global__ __launch_bounds__(256)
void aggregate_kernel(float* __restrict__ out,
                      const float* __restrict__ b_pos,
                      const float* __restrict__ b_neg, int n) {
    int warp = (blockIdx.x * blockDim.x + threadIdx.x) >> 5;
    int lane = threadIdx.x & 31;
    int half = lane >> 4;
    int l16  = lane & 15;
    int segi = warp * 2 + half;
    if (segi >= 2 * n) return;
    int sign = (segi >= n);
    int d = sign ? segi - n : segi;
    int seg = sign * NNODES + d;
    int h = l16 >> 1;

    float er_h = g_er[(size_t)sign * NNODES * HEADS + (size_t)d * HEADS + h];
    const float* elb = g_el + (size_t)sign * NNODES * HEADS;
    const __half* fb = g_feat16 + (size_t)sign * NNODES * HIDDEN;

    int start = g_off[seg];
    int end   = g_cur[seg];

    float acc[8] = {};
    float den = 0.f;

#define ACC8(r, ex) do {                                                       \
        float2 t;                                                              \
        t = __half22float2(*(__half2*)&(r).x);                                 \
        acc[0] = fmaf((ex), t.x, acc[0]); acc[1] = fmaf((ex), t.y, acc[1]);    \
        t = __half22float2(*(__half2*)&(r).y);                                 \
        acc[2] = fmaf((ex), t.x, acc[2]); acc[3] = fmaf((ex), t.y, acc[3]);    \
        t = __half22float2(*(__half2*)&(r).z);                                 \
        acc[4] = fmaf((ex), t.x, acc[4]); acc[5] = fmaf((ex), t.y, acc[5]);    \
        t = __half22float2(*(__half2*)&(r).w);                                 \
        acc[6] = fmaf((ex), t.x, acc[6]); acc[7] = fmaf((ex), t.y, acc[7]);    \
    } while (0)

    int k = start;
    for (; k + 1 < end; k += 2) {
        int s0 = g_srcs[k];
        int s1 = g_srcs[k + 1];
        float eh0 = elb[(size_t)s0 * HEADS + h] + er_h;
        float eh1 = elb[(size_t)s1 * HEADS + h] + er_h;
        uint4 r0 = *(const uint4*)&fb[(size_t)s0 * HIDDEN + l16 * 8];
        uint4 r1 = *(const uint4*)&fb[(size_t)s1 * HIDDEN + l16 * 8];
        eh0 = (eh0 > 0.f) ? eh0 : NEG_SLOPE * eh0;
        eh1 = (eh1 > 0.f) ? eh1 : NEG_SLOPE * eh1;
        float ex0 = __expf(eh0);
        float ex1 = __expf(eh1);
        den += ex0 + ex1;
        ACC8(r0, ex0);
        ACC8(r1, ex1);
    }
    if (k < end) {
        int s = g_srcs[k];
        float eh = elb[(size_t)s * HEADS + h] + er_h;
        eh = (eh > 0.f) ? eh : NEG_SLOPE * eh;
        float ex = __expf(eh);
        den += ex;
        uint4 r = *(const uint4*)&fb[(size_t)s * HIDDEN + l16 * 8];
        ACC8(r, ex);
    }
#undef ACC8

    float inv = (den > 0.f) ? (1.0f / den) : 0.0f;
    const float* bias = sign ? b_neg : b_pos;
    float* orow = &out[((size_t)sign * n + d) * HIDDEN + l16 * 8];
    float4 o0, o1;
    const float4 bv0 = *(const float4*)(bias + l16 * 8);
    const float4 bv1 = *(const float4*)(bias + l16 * 8 + 4);
    o0.x = acc[0] * inv + bv0.x; o0.y = acc[1] * inv + bv0.y;
    o0.z = acc[2] * inv + bv0.z; o0.w = acc[3] * inv + bv0.w;
    o1.x = acc[4] * inv + bv1.x; o1.y = acc[5] * inv + bv1.y;
    o1.z = acc[6] * inv + bv1.z; o1.w = acc[7] * inv + bv1.w;
    *(float4*)orow = o0;
    *(float4*)(orow + 4) = o1;
}

// ------------------------- fp16 helpers --------------------------------------
__device__ __forceinline__ uint32_t f2h2(float lo, float hi) {
    __half2 h = __floats2half2_rn(lo, hi);
    return *(uint32_t*)&h;
}

#define MMA_F16(cr, a, b)                                                      \
    asm volatile("mma.sync.aligned.m16n8k16.row.col.f32.f16.f16.f32 "          \
                 "{%0,%1,%2,%3},{%4,%5,%6,%7},{%8,%9},{%0,%1,%2,%3};"          \
                 : "+f"((cr)[0]), "+f"((cr)[1]), "+f"((cr)[2]), "+f"((cr)[3])  \
                 : "r"((a)[0]), "r"((a)[1]), "r"((a)[2]), "r"((a)[3]),         \
                   "r"((b)[0]), "r"((b)[1]))

// ------------------------- tensor-core fp16 GEMM (feature pass) --------------
__global__ __launch_bounds__(256, 2)
void gemm_feat(const float* __restrict__ A0, int M, int K,
               const float* __restrict__ B0, const float* __restrict__ B1,
               __half* __restrict__ C0, __half* __restrict__ C1,
               const float* __restrict__ al0, const float* __restrict__ ar0,
               float* __restrict__ el0, float* __restrict__ er0,
               const float* __restrict__ al1, const float* __restrict__ ar1,
               float* __restrict__ el1, float* __restrict__ er1) {
    constexpr int NT = 128;
    constexpr int ASTR = 12;
    constexpr int BSTR = NT + 8;
    constexpr int WN   = NT / 2;
    constexpr int NJ   = WN / 8;
    constexpr int ASZ  = 128 * ASTR;
    constexpr int BSZ  = 8 * BSTR;

    __shared__ __align__(16) uint32_t As[2 * ASZ];
    __shared__ __align__(16) uint32_t Bs[2 * BSZ];

    const float* B  = B0;
    __half*      C  = C0;
    const float* al = al0; const float* ar = ar0;
    float*       el = el0; float*       er = er0;
    if (blockIdx.y == 1) { B = B1; C = C1; al = al1; ar = ar1; el = el1; er = er1; }

    const int tid  = threadIdx.x;
    const int wid  = tid >> 5;
    const int lane = tid & 31;
    const int g    = lane >> 2;
    const int tig  = lane & 3;
    const int wm   = wid & 3;
    const int wn   = wid >> 2;
    const int m0   = blockIdx.x * 128;

    float c[2][NJ][4];
#pragma unroll
    for (int mi = 0; mi < 2; mi++)
#pragma unroll
        for (int nj = 0; nj < NJ; nj++)
#pragma unroll
            for (int q = 0; q < 4; q++) c[mi][nj][q] = 0.0f;

    float4 pa[2], pb[2];

#define LOAD_A(k0, i, dstv) do {                                               \
        int idx = tid + (i) * 256;                                             \
        int row = idx >> 2; int kk = (idx & 3) * 4;                            \
        int grow = m0 + row;                                                   \
        if (grow < M) {                                                        \
            dstv = *(const float4*)(A0 + (size_t)grow * 128 + (k0) + kk);      \
        } else dstv = make_float4(0.f, 0.f, 0.f, 0.f);                         \
    } while (0)
#define LOAD_B(k0) do {                                                        \
        int kp = tid >> 5, n4 = (tid & 31) * 4;                                \
        pb[0] = *(const float4*)(B + (size_t)((k0) + 2 * kp)     * NT + n4);   \
        pb[1] = *(const float4*)(B + (size_t)((k0) + 2 * kp + 1) * NT + n4);   \
    } while (0)
#define COMMIT(p) do {                                                         \
        _Pragma("unroll")                                                      \
        for (int i = 0; i < 2; i++) {                                          \
            int idx = tid + i * 256;                                           \
            int row = idx >> 2; int kp0 = (idx & 3) * 2;                       \
            uint2 t = make_uint2(f2h2(pa[i].x, pa[i].y), f2h2(pa[i].z, pa[i].w)); \
            *(uint2*)&As[(p) * ASZ + row * ASTR + kp0] = t;                    \
        }                                                                      \
        {                                                                      \
            int kp = tid >> 5, n4 = (tid & 31) * 4;                            \
            uint4 t = make_uint4(f2h2(pb[0].x, pb[1].x), f2h2(pb[0].y, pb[1].y), \
                                 f2h2(pb[0].z, pb[1].z), f2h2(pb[0].w, pb[1].w)); \
            *(uint4*)&Bs[(p) * BSZ + kp * BSTR + n4] = t;                      \
        }                                                                      \
    } while (0)

    LOAD_A(0, 0, pa[0]); LOAD_A(0, 1, pa[1]);
    LOAD_B(0);
    COMMIT(0);
    __syncthreads();
    if (K > 16) {
        LOAD_A(16, 0, pa[0]); LOAD_A(16, 1, pa[1]);
        LOAD_B(16);
    }

    int p = 0;
    for (int k0 = 0; k0 < K; k0 += 16) {
        if (k0 + 16 < K) {
            COMMIT(p ^ 1);
            if (k0 + 32 < K) {
                LOAD_A(k0 + 32, 0, pa[0]); LOAD_A(k0 + 32, 1, pa[1]);
                LOAD_B(k0 + 32);
            }
        }
        const uint32_t* Ap = &As[p * ASZ];
        const uint32_t* Bp = &Bs[p * BSZ];
        uint32_t af[2][4];
#pragma unroll
        for (int mi = 0; mi < 2; mi++) {
            int mb = wm * 32 + mi * 16;
            af[mi][0] = Ap[(mb + g)     * ASTR + tig];
            af[mi][1] = Ap[(mb + 8 + g) * ASTR + tig];
            af[mi][2] = Ap[(mb + g)     * ASTR + tig + 4];
            af[mi][3] = Ap[(mb + 8 + g) * ASTR + tig + 4];
        }
        uint32_t bf[NJ][2];
#pragma unroll
        for (int nj = 0; nj < NJ; nj++) {
            int nb = wn * WN + nj * 8;
            bf[nj][0] = Bp[tig       * BSTR + nb + g];
            bf[nj][1] = Bp[(tig + 4) * BSTR + nb + g];
        }
#pragma unroll
        for (int mi = 0; mi < 2; mi++)
#pragma unroll
            for (int nj = 0; nj < NJ; nj++)
                MMA_F16(c[mi][nj], af[mi], bf[nj]);
        __syncthreads();
        p ^= 1;
    }
#undef LOAD_A
#undef LOAD_B
#undef COMMIT

    // ---- fused el/er epilogue ----
#pragma unroll
    for (int mi = 0; mi < 2; mi++) {
#pragma unroll
        for (int h = 0; h < 4; h++) {
            float e0 = 0.f, e1 = 0.f, r0v = 0.f, r1v = 0.f;
#pragma unroll
            for (int q = 0; q < 2; q++) {
                int nj = 2 * h + q;
                int col = wn * 64 + nj * 8 + 2 * tig;
                float a0 = al[col], a1 = al[col + 1];
                float b0 = ar[col], b1 = ar[col + 1];
                e0  += c[mi][nj][0] * a0 + c[mi][nj][1] * a1;
                e1  += c[mi][nj][2] * a0 + c[mi][nj][3] * a1;
                r0v += c[mi][nj][0] * b0 + c[mi][nj][1] * b1;
                r1v += c[mi][nj][2] * b0 + c[mi][nj][3] * b1;
            }
            e0  += __shfl_xor_sync(0xffffffffu, e0, 1);
            e0  += __shfl_xor_sync(0xffffffffu, e0, 2);
            e1  += __shfl_xor_sync(0xffffffffu, e1, 1);
            e1  += __shfl_xor_sync(0xffffffffu, e1, 2);
            r0v += __shfl_xor_sync(0xffffffffu, r0v, 1);
            r0v += __shfl_xor_sync(0xffffffffu, r0v, 2);
            r1v += __shfl_xor_sync(0xffffffffu, r1v, 1);
            r1v += __shfl_xor_sync(0xffffffffu, r1v, 2);
            if (tig == 0) {
                int hg = wn * 4 + h;
                int ra = m0 + wm * 32 + mi * 16 + g;
                int rb = ra + 8;
                if (ra < M) { el[ra * HEADS + hg] = e0;  er[ra * HEADS + hg] = r0v; }
                if (rb < M) { el[rb * HEADS + hg] = e1;  er[rb * HEADS + hg] = r1v; }
            }
        }
    }

    // ---- store C (fp16) ----
#pragma unroll
    for (int mi = 0; mi < 2; mi++) {
        int ra = m0 + wm * 32 + mi * 16 + g;
        int rb = ra + 8;
#pragma unroll
        for (int nj = 0; nj < NJ; nj++) {
            int col = wn * WN + nj * 8 + 2 * tig;
            if (ra < M) *(__half2*)&C[(size_t)ra * NT + col] =
                __floats2half2_rn(c[mi][nj][0], c[mi][nj][1]);
            if (rb < M) *(__half2*)&C[(size_t)rb * NT + col] =
                __floats2half2_rn(c[mi][nj][2], c[mi][nj][3]);
        }
    }
}

// ------------------------- fused MLP kernel ----------------------------------
// h_final[M,64] = relu([h_pos|h_neg][M,256] @ W1[256,128] + b1) @ W2[128,64] + b2
__global__ __launch_bounds__(256, 2)
void mlp_fused(const float* __restrict__ A0, const float* __restrict__ A1,
               int M,
               const float* __restrict__ W1, const float* __restrict__ b1,
               const float* __restrict__ W2, const float* __restrict__ b2,
               float* __restrict__ outF) {
    constexpr int NT = 128;
    constexpr int ASTR = 12;
    constexpr int BSTR = NT + 8;
    constexpr int NJ   = 8;
    constexpr int ASZ  = 128 * ASTR;
    constexpr int BSZ  = 8 * BSTR;
    __shared__ __align__(16) uint32_t smem[12288];
    uint32_t* As  = smem;
    uint32_t* Bs  = smem + 2 * ASZ;
    uint32_t* Hs  = smem;              // [128 rows][64 kpairs], swizzled
    uint32_t* B2s = smem + 8192;       // [64 kpairs][64 n], swizzled

    const int tid  = threadIdx.x;
    const int wid  = tid >> 5;
    const int lane = tid & 31;
    const int g    = lane >> 2;
    const int tig  = lane & 3;
    const int wm   = wid & 3;
    const int wn   = wid >> 2;
    const int m0   = blockIdx.x * 128;

    float c[2][NJ][4];
#pragma unroll
    for (int mi = 0; mi < 2; mi++)
#pragma unroll
        for (int nj = 0; nj < NJ; nj++)
#pragma unroll
            for (int q = 0; q < 4; q++) c[mi][nj][q] = 0.0f;

    float4 pa[2], pb[2];

#define LOAD_A(k0, i, dstv) do {                                               \
        int idx = tid + (i) * 256;                                             \
        int row = idx >> 2; int kk = (idx & 3) * 4;                            \
        int grow = m0 + row;                                                   \
        if (grow < M) {                                                        \
            int kg = (k0) + kk;                                                \
            const float* srcp = (kg < 128) ? (A0 + (size_t)grow * 128 + kg)    \
                                           : (A1 + (size_t)grow * 128 + (kg - 128)); \
            dstv = *(const float4*)srcp;                                       \
        } else dstv = make_float4(0.f, 0.f, 0.f, 0.f);                         \
    } while (0)
#define LOAD_B(k0) do {                                                        \
        int kp = tid >> 5, n4 = (tid & 31) * 4;                                \
        pb[0] = *(const float4*)(W1 + (size_t)((k0) + 2 * kp)     * NT + n4);  \
        pb[1] = *(const float4*)(W1 + (size_t)((k0) + 2 * kp + 1) * NT + n4);  \
    } while (0)
#define COMMIT(p) do {                                                         \
        _Pragma("unroll")                                                      \
        for (int i = 0; i < 2; i++) {                                          \
            int idx = tid + i * 256;                                           \
            int row = idx >> 2; int kp0 = (idx & 3) * 2;                       \
            uint2 t = make_uint2(f2h2(pa[i].x, pa[i].y), f2h2(pa[i].z, pa[i].w)); \
            *(uint2*)&As[(p) * ASZ + row * ASTR + kp0] = t;                    \
        }                                                                      \
        {                                                                      \
            int kp = tid >> 5, n4 = (tid & 31) * 4;                            \
            uint4 t = make_uint4(f2h2(pb[0].x, pb[1].x), f2h2(pb[0].y, pb[1].y), \
                                 f2h2(pb[0].z, pb[1].z), f2h2(pb[0].w, pb[1].w)); \
            *(uint4*)&Bs[(p) * BSZ + kp * BSTR + n4] = t;                      \
        }                                                                      \
    } while (0)

    LOAD_A(0, 0, pa[0]); LOAD_A(0, 1, pa[1]);
    LOAD_B(0);
    COMMIT(0);
    __syncthreads();
    LOAD_A(16, 0, pa[0]); LOAD_A(16, 1, pa[1]);
    LOAD_B(16);

    int p = 0;
    for (int k0 = 0; k0 < 256; k0 += 16) {
        if (k0 + 16 < 256) {
            COMMIT(p ^ 1);
            if (k0 + 32 < 256) {
                LOAD_A(k0 + 32, 0, pa[0]); LOAD_A(k0 + 32, 1, pa[1]);
                LOAD_B(k0 + 32);
            }
        }
        const uint32_t* Ap = &As[p * ASZ];
        const uint32_t* Bp = &Bs[p * BSZ];
        uint32_t af[2][4];
#pragma unroll
        for (int mi = 0; mi < 2; mi++) {
            int mb = wm * 32 + mi * 16;
            af[mi][0] = Ap[(mb + g)     * ASTR + tig];
            af[mi][1] = Ap[(mb + 8 + g) * ASTR + tig];
            af[mi][2] = Ap[(mb + g)     * ASTR + tig + 4];
            af[mi][3] = Ap[(mb + 8 + g) * ASTR + tig + 4];
        }
        uint32_t bf[NJ][2];
#pragma unroll
        for (int nj = 0; nj < NJ; nj++) {
            int nb = wn * 64 + nj * 8;
            bf[nj][0] = Bp[tig       * BSTR + nb + g];
            bf[nj][1] = Bp[(tig + 4) * BSTR + nb + g];
        }
#pragma unroll
        for (int mi = 0; mi < 2; mi++)
#pragma unroll
            for (int nj = 0; nj < NJ; nj++)
                MMA_F16(c[mi][nj], af[mi], bf[nj]);
        __syncthreads();
        p ^= 1;
    }
#undef LOAD_A
#undef LOAD_B
#undef COMMIT

    // ---- write hidden (bias + relu, fp16) into Hs, swizzle kp ^ ((m&7)<<2) ----
#pragma unroll
    for (int mi = 0; mi < 2; mi++) {
        int ra = wm * 32 + mi * 16 + g;
        int rb = ra + 8;
#pragma unroll
        for (int nj = 0; nj < NJ; nj++) {
            int col = wn * 64 + nj * 8 + 2 * tig;
            float bx = b1[col], by = b1[col + 1];
            float v0 = fmaxf(c[mi][nj][0] + bx, 0.f);
            float v1 = fmaxf(c[mi][nj][1] + by, 0.f);
            float v2 = fmaxf(c[mi][nj][2] + bx, 0.f);
            float v3 = fmaxf(c[mi][nj][3] + by, 0.f);
            int cp = wn * 32 + nj * 4 + tig;
            Hs[ra * 64 + (cp ^ (g << 2))] = f2h2(v0, v1);
            Hs[rb * 64 + (cp ^ (g << 2))] = f2h2(v2, v3);
        }
    }

    // ---- load W2 [128,64] into B2s, swizzle n ^ ((kp&3)<<3) ----
#pragma unroll
    for (int i = 0; i < 4; i++) {
        int idx = tid + i * 256;
        int kp = idx >> 4;
        int n4 = (idx & 15) * 4;
        float4 ev = *(const float4*)(W2 + (size_t)(2 * kp)     * 64 + n4);
        float4 ov = *(const float4*)(W2 + (size_t)(2 * kp + 1) * 64 + n4);
        uint4 t = make_uint4(f2h2(ev.x, ov.x), f2h2(ev.y, ov.y),
                             f2h2(ev.z, ov.z), f2h2(ev.w, ov.w));
        *(uint4*)&B2s[kp * 64 + (n4 ^ ((kp & 3) << 3))] = t;
    }
    __syncthreads();

    // ---- stage 2: [128,128] @ [128,64], 8 k16 steps ----
    float c2[2][4][4];
#pragma unroll
    for (int mi = 0; mi < 2; mi++)
#pragma unroll
        for (int nj = 0; nj < 4; nj++)
#pragma unroll
            for (int q = 0; q < 4; q++) c2[mi][nj][q] = 0.0f;

#pragma unroll
    for (int ks8 = 0; ks8 < 8; ks8++) {
        int kp0 = ks8 * 8;
        uint32_t af[2][4];
#pragma unroll
        for (int mi = 0; mi < 2; mi++) {
            int mb = wm * 32 + mi * 16;
            af[mi][0] = Hs[(mb + g)     * 64 + ((kp0 + tig)     ^ (g << 2))];
            af[mi][1] = Hs[(mb + 8 + g) * 64 + ((kp0 + tig)     ^ (g << 2))];
            af[mi][2] = Hs[(mb + g)     * 64 + ((kp0 + tig + 4) ^ (g << 2))];
            af[mi][3] = Hs[(mb + 8 + g) * 64 + ((kp0 + tig + 4) ^ (g << 2))];
        }
        uint32_t bf[4][2];
#pragma unroll
        for (int nj = 0; nj < 4; nj++) {
            int nb = wn * 32 + nj * 8 + g;
            bf[nj][0] = B2s[(kp0 + tig)     * 64 + (nb ^ (tig << 3))];
            bf[nj][1] = B2s[(kp0 + tig + 4) * 64 + (nb ^ (tig << 3))];
        }
#pragma unroll
        for (int mi = 0; mi < 2; mi++)
#pragma unroll
            for (int nj = 0; nj < 4; nj++)
                MMA_F16(c2[mi][nj], af[mi], bf[nj]);
    }

    // ---- store h_final (fp32, + b2) ----
#pragma unroll
    for (int mi = 0; mi < 2; mi++) {
        int ra = m0 + wm * 32 + mi * 16 + g;
        int rb = ra + 8;
#pragma unroll
        for (int nj = 0; nj < 4; nj++) {
            int col = wn * 32 + nj * 8 + 2 * tig;
            float bx = b2[col], by = b2[col + 1];
            if (ra < M) *(float2*)&outF[(size_t)ra * 64 + col] =
                make_float2(c2[mi][nj][0] + bx, c2[mi][nj][1] + by);
            if (rb < M) *(float2*)&outF[(size_t)rb * 64 + col] =
                make_float2(c2[mi][nj][2] + bx, c2[mi][nj][3] + by);
        }
    }
}

// ------------------------- launcher ------------------------------------------
extern "C" void kernel_launch(void* const* d_in, const int* in_sizes, int n_in,
                              void* d_out, int out_size) {
    const float* features = (const float*)d_in[0];
    const int*   pos_src  = (const int*)d_in[1];
    const int*   pos_dst  = (const int*)d_in[2];
    const int*   neg_src  = (const int*)d_in[3];
    const int*   neg_dst  = (const int*)d_in[4];
    const float* W_pos    = (const float*)d_in[5];
    const float* al_pos   = (const float*)d_in[6];
    const float* ar_pos   = (const float*)d_in[7];
    const float* b_pos    = (const float*)d_in[8];
    const float* W_neg    = (const float*)d_in[9];
    const float* al_neg   = (const float*)d_in[10];
    const float* ar_neg   = (const float*)d_in[11];
    const float* b_neg    = (const float*)d_in[12];
    const float* W1       = (const float*)d_in[13];
    const float* b1       = (const float*)d_in[14];
    const float* W2       = (const float*)d_in[15];
    const float* b2       = (const float*)d_in[16];
    float* out = (float*)d_out;

    int n = in_sizes[0] / HIDDEN;   // 100000
    int e = in_sizes[1];            // 600000

    void* p;
    cudaGetSymbolAddress(&p, g_feat16); __half* featp = (__half*)p;
    cudaGetSymbolAddress(&p, g_el);     float*  elp   = (float*)p;
    cudaGetSymbolAddress(&p, g_er);     float*  erp   = (float*)p;

    float* h_pos   = out;
    float* h_neg   = out + (size_t)n * HIDDEN;
    float* h_final = out + (size_t)2 * n * HIDDEN;

    int gb   = (n + 127) / 128;
    int nseg = 2 * n;
    int nb   = (nseg + 1023) / 1024;

    // Fork a side stream for the CSR build (independent of the feature GEMMs).
    cudaStream_t s1;
    cudaEvent_t ev_fork, ev_join;
    cudaStreamCreateWithFlags(&s1, cudaStreamNonBlocking);
    cudaEventCreateWithFlags(&ev_fork, cudaEventDisableTiming);
    cudaEventCreateWithFlags(&ev_join, cudaEventDisableTiming);

    cudaEventRecord(ev_fork, 0);
    cudaStreamWaitEvent(s1, ev_fork, 0);

    // --- side stream: CSR build (3 kernels; g_cnt/g_total self-reinitializing) ---
    hist_kernel<<<(2 * e + 255) / 256, 256, 0, s1>>>(pos_dst, neg_dst, e);
    scan_fused<<<nb, 256, 0, s1>>>(nseg);
    scatter_kernel<<<(2 * e + 255) / 256, 256, 0, s1>>>(pos_src, pos_dst, neg_src, neg_dst, e);
    cudaEventRecord(ev_join, s1);

    // --- main stream: feature transform GEMMs (fp16 MMA, both signs) ---
    {
        dim3 grid(gb, 2);
        gemm_feat<<<grid, 256>>>(
            features, n, HIDDEN,
            W_pos, W_neg,
            featp, featp + (size_t)NNODES * HIDDEN,
            al_pos, ar_pos, elp, erp,
            al_neg, ar_neg,
            elp + (size_t)NNODES * HEADS, erp + (size_t)NNODES * HEADS);
    }

    // join: aggregation needs both CSR and features
    cudaStreamWaitEvent(0, ev_join, 0);

    // --- fused softmax + aggregation + normalize + bias (h_pos | h_neg) ---
    {
        int nwarps = (2 * n + 1) / 2;            // half-warp per segment
        int gwb = (nwarps + 7) / 8;              // 8 warps per 256-thread block
        aggregate_kernel<<<gwb, 256>>>(out, b_pos, b_neg, n);
    }

    // --- fused MLP: h_final = relu([h_pos|h_neg] @ W1 + b1) @ W2 + b2 ---
    mlp_fused<<<gb, 256>>>(h_pos, h_neg, n, W1, b1, W2, b2, h_final);
}